// round 9
// baseline (speedup 1.0000x reference)
#include <cuda_runtime.h>
#include <cuda_bf16.h>
#include <cstdint>

#define B_ 4
#define S_ 2048
#define H_ 16
#define D_ 64
#define HID_ 1024
#define NROWS_ (B_*S_)
#define APLANE ((size_t)NROWS_*HID_)
#define WPLANE ((size_t)HID_*HID_)

// ------------------------- device scratch (no allocs) -----------------------
__device__ __nv_bfloat16 g_qhi[APLANE];  // [B*S][H*64], q pre-scaled
__device__ __nv_bfloat16 g_qlo[APLANE];
__device__ __nv_bfloat16 g_khi[APLANE];
__device__ __nv_bfloat16 g_klo[APLANE];
__device__ __nv_bfloat16 g_vhi[APLANE];
__device__ __nv_bfloat16 g_vlo[APLANE];
__device__ __nv_bfloat16 g_ahi[3*APLANE];  // GEMM A planes (q/k/v in; attn out->plane0)
__device__ __nv_bfloat16 g_alo[3*APLANE];
__device__ __nv_bfloat16 g_whi[4*WPLANE]; // weight planes [N][K]; plane3 = wo
__device__ __nv_bfloat16 g_wlo[4*WPLANE];
__device__ uint32_t g_mb[(size_t)B_*S_*(S_/32)];
__device__ int g_mask_mode;

// ------------------------- helpers ------------------------------------------
__device__ __forceinline__ uint32_t smem_u32(const void* p) {
    uint32_t a;
    asm("{ .reg .u64 t; cvta.to.shared.u64 t, %1; cvt.u32.u64 %0, t; }"
        : "=r"(a) : "l"(p));
    return a;
}
__device__ __forceinline__ void cp16(uint32_t dst, const void* src) {
    asm volatile("cp.async.cg.shared.global [%0], [%1], 16;\n" :: "r"(dst), "l"(src));
}
#define CP_COMMIT() asm volatile("cp.async.commit_group;\n" ::: "memory")

__device__ __forceinline__ void ldsm4(uint32_t* r, uint32_t addr) {
    asm volatile("ldmatrix.sync.aligned.m8n8.x4.shared.b16 {%0,%1,%2,%3}, [%4];"
        : "=r"(r[0]), "=r"(r[1]), "=r"(r[2]), "=r"(r[3]) : "r"(addr));
}
__device__ __forceinline__ void ldsm4t(uint32_t* r, uint32_t addr) {
    asm volatile("ldmatrix.sync.aligned.m8n8.x4.trans.shared.b16 {%0,%1,%2,%3}, [%4];"
        : "=r"(r[0]), "=r"(r[1]), "=r"(r[2]), "=r"(r[3]) : "r"(addr));
}
__device__ __forceinline__ void mma16816(float* d, const uint32_t* a, const uint32_t* b) {
    asm volatile("mma.sync.aligned.m16n8k16.row.col.f32.bf16.bf16.f32 "
        "{%0,%1,%2,%3}, {%4,%5,%6,%7}, {%8,%9}, {%0,%1,%2,%3};"
        : "+f"(d[0]), "+f"(d[1]), "+f"(d[2]), "+f"(d[3])
        : "r"(a[0]), "r"(a[1]), "r"(a[2]), "r"(a[3]), "r"(b[0]), "r"(b[1]));
}
__device__ __forceinline__ uint32_t packbf(float e0, float e1) {
    uint32_t d;
    asm("cvt.rn.bf16x2.f32 %0, %1, %2;" : "=r"(d) : "f"(e1), "f"(e0));
    return d;
}
__device__ __forceinline__ float bfres(float x) {
    __nv_bfloat16 h = __float2bfloat16(x);
    return x - __bfloat162float(h);
}

// ------------------------- mask detect + pack --------------------------------
__global__ void detect_mask_kernel(const unsigned int* __restrict__ m) {
    __shared__ int sF, sO;
    if (threadIdx.x == 0) { sF = 0; sO = 0; }
    __syncthreads();
    bool f = false, o = false;
    for (int i = threadIdx.x; i < 2048; i += 256) {
        unsigned int w = m[i];
        if (w == 0u || w == 1u) continue;
        if (w == 0x3f800000u) f = true; else o = true;
    }
    if (f) sF = 1;
    if (o) sO = 1;
    __syncthreads();
    if (threadIdx.x == 0) g_mask_mode = sO ? 1 : (sF ? 2 : 0);
}

__global__ __launch_bounds__(256) void pack_mask(const void* __restrict__ mask) {
    int mode = g_mask_mode;
    #pragma unroll
    for (int p = 0; p < 4; p++) {
        int widx = blockIdx.x * 1024 + p * 256 + threadIdx.x;
        uint32_t bits = 0;
        if (mode == 1) {
            const uchar4* pp = (const uchar4*)mask + (size_t)widx * 8;
            #pragma unroll
            for (int q = 0; q < 8; q++) {
                uchar4 v = pp[q];
                bits |= (uint32_t)(v.x != 0) << (4*q)
                     |  (uint32_t)(v.y != 0) << (4*q+1)
                     |  (uint32_t)(v.z != 0) << (4*q+2)
                     |  (uint32_t)(v.w != 0) << (4*q+3);
            }
        } else if (mode == 2) {
            const float4* pp = (const float4*)mask + (size_t)widx * 8;
            #pragma unroll
            for (int q = 0; q < 8; q++) {
                float4 v = pp[q];
                bits |= (uint32_t)(v.x != 0.f) << (4*q)
                     |  (uint32_t)(v.y != 0.f) << (4*q+1)
                     |  (uint32_t)(v.z != 0.f) << (4*q+2)
                     |  (uint32_t)(v.w != 0.f) << (4*q+3);
            }
        } else {
            const int4* pp = (const int4*)mask + (size_t)widx * 8;
            #pragma unroll
            for (int q = 0; q < 8; q++) {
                int4 v = pp[q];
                bits |= (uint32_t)(v.x != 0) << (4*q)
                     |  (uint32_t)(v.y != 0) << (4*q+1)
                     |  (uint32_t)(v.z != 0) << (4*q+2)
                     |  (uint32_t)(v.w != 0) << (4*q+3);
            }
        }
        g_mb[widx] = bits;
    }
}

// ------------------------- prep kernels --------------------------------------
__global__ __launch_bounds__(256) void split3_kernel(
    const float4* __restrict__ x0, const float4* __restrict__ x1,
    const float4* __restrict__ x2)
{
    int pl = blockIdx.y;
    const float4* __restrict__ src = (pl == 0) ? x0 : (pl == 1) ? x1 : x2;
    __nv_bfloat162* hi = reinterpret_cast<__nv_bfloat162*>(g_ahi + pl * APLANE);
    __nv_bfloat162* lo = reinterpret_cast<__nv_bfloat162*>(g_alo + pl * APLANE);
    #pragma unroll
    for (int p = 0; p < 4; p++) {
        size_t i = (size_t)blockIdx.x * 1024 + p * 256 + threadIdx.x;
        float4 v = src[i];
        __nv_bfloat16 h0 = __float2bfloat16(v.x), h1 = __float2bfloat16(v.y);
        __nv_bfloat16 h2 = __float2bfloat16(v.z), h3 = __float2bfloat16(v.w);
        __nv_bfloat162 a, b;
        a.x = h0; a.y = h1; b.x = h2; b.y = h3;
        hi[i*2] = a; hi[i*2+1] = b;
        a.x = __float2bfloat16(v.x - __bfloat162float(h0));
        a.y = __float2bfloat16(v.y - __bfloat162float(h1));
        b.x = __float2bfloat16(v.z - __bfloat162float(h2));
        b.y = __float2bfloat16(v.w - __bfloat162float(h3));
        lo[i*2] = a; lo[i*2+1] = b;
    }
}

// 4 weight planes: 0..2 = wq/wk/wv ([H,HID,D] gather), 3 = wo ([K,N] transpose)
__global__ __launch_bounds__(256) void prep_w4(
    const float* __restrict__ w0, const float* __restrict__ w1,
    const float* __restrict__ w2, const float* __restrict__ w3)
{
    int pl = blockIdx.z;
    int k = blockIdx.x * 256 + threadIdx.x;
    int n = blockIdx.y;
    float v;
    if (pl < 3) {
        const float* __restrict__ w = (pl == 0) ? w0 : (pl == 1) ? w1 : w2;
        float scale = (pl == 0) ? 0.125f : 1.0f;
        int h = n >> 6, d = n & 63;
        v = w[((size_t)h * HID_ + k) * D_ + d] * scale;
    } else {
        v = w3[(size_t)k * HID_ + n];
    }
    __nv_bfloat16 hi = __float2bfloat16(v);
    g_whi[pl * WPLANE + (size_t)n * HID_ + k] = hi;
    g_wlo[pl * WPLANE + (size_t)n * HID_ + k] = __float2bfloat16(v - __bfloat162float(hi));
}

// ------------------------- HMMA GEMM -----------------------------------------
#define STG 32768
#define OFF_ALO 8192
#define OFF_BHI 16384
#define OFF_BLO 24576

__device__ __forceinline__ uint32_t taddr(uint32_t base, int row, int chunk) {
    return base + row * 64 + ((chunk ^ ((row >> 1) & 3)) << 4);
}

__device__ __forceinline__ void load_tile(uint32_t dstbase,
    const __nv_bfloat16* __restrict__ src, int row0, int k0, int tid)
{
    #pragma unroll
    for (int p = 0; p < 2; p++) {
        int idx = tid + p * 256;
        int row = idx >> 2, ch = idx & 3;
        cp16(taddr(dstbase, row, ch),
             src + (size_t)(row0 + row) * HID_ + k0 + ch * 8);
    }
}

__device__ __forceinline__ void gemm_body(
    const __nv_bfloat16* __restrict__ Ahi, const __nv_bfloat16* __restrict__ Alo,
    const __nv_bfloat16* __restrict__ Whi, const __nv_bfloat16* __restrict__ Wlo,
    const float* __restrict__ bias, float bscale,
    float* __restrict__ out_ext, int sel)
{
    extern __shared__ char raw[];
    uint32_t sb = smem_u32(raw);

    int tid = threadIdx.x, lane = tid & 31, wid = tid >> 5;
    int wm = wid & 3, wn = wid >> 2;
    int m0 = blockIdx.x * 128, n0 = blockIdx.y * 128;
    int lrow = lane & 15, lsel = lane >> 4;

    float acc[2][8][4];
    #pragma unroll
    for (int a = 0; a < 2; a++)
        #pragma unroll
        for (int b = 0; b < 8; b++)
            #pragma unroll
            for (int c = 0; c < 4; c++) acc[a][b][c] = 0.f;

    load_tile(sb,            Ahi, m0, 0, tid);
    load_tile(sb + OFF_ALO,  Alo, m0, 0, tid);
    load_tile(sb + OFF_BHI,  Whi, n0, 0, tid);
    load_tile(sb + OFF_BLO,  Wlo, n0, 0, tid);
    CP_COMMIT();

    const int NST = HID_ / 32;
    for (int i = 0; i < NST; i++) {
        if (i + 1 < NST) {
            uint32_t nb = sb + (uint32_t)((i + 1) & 1) * STG;
            int k0 = (i + 1) * 32;
            load_tile(nb,           Ahi, m0, k0, tid);
            load_tile(nb + OFF_ALO, Alo, m0, k0, tid);
            load_tile(nb + OFF_BHI, Whi, n0, k0, tid);
            load_tile(nb + OFF_BLO, Wlo, n0, k0, tid);
            CP_COMMIT();
            asm volatile("cp.async.wait_group 1;" ::: "memory");
        } else {
            asm volatile("cp.async.wait_group 0;" ::: "memory");
        }
        __syncthreads();

        uint32_t buf = sb + (uint32_t)(i & 1) * STG;
        #pragma unroll
        for (int kk = 0; kk < 2; kk++) {
            int chunk = (kk << 1) + lsel;
            uint32_t ahi[2][4], alo[2][4];
            #pragma unroll
            for (int mf = 0; mf < 2; mf++) {
                int row = wm * 32 + mf * 16 + lrow;
                uint32_t ad = taddr(buf, row, chunk);
                ldsm4(ahi[mf], ad);
                ldsm4(alo[mf], ad + OFF_ALO);
            }
            uint32_t bhi[8][2], blo[8][2];
            #pragma unroll
            for (int j = 0; j < 4; j++) {
                int row = wn * 64 + j * 16 + lrow;
                uint32_t bd = taddr(buf + OFF_BHI, row, chunk);
                uint32_t t4[4];
                ldsm4(t4, bd);
                bhi[2*j][0] = t4[0]; bhi[2*j+1][0] = t4[1];
                bhi[2*j][1] = t4[2]; bhi[2*j+1][1] = t4[3];
                ldsm4(t4, bd + 8192);
                blo[2*j][0] = t4[0]; blo[2*j+1][0] = t4[1];
                blo[2*j][1] = t4[2]; blo[2*j+1][1] = t4[3];
            }
            // Product-kind outermost: 16 independent MMAs between reuses of the
            // same accumulator (asm volatile pins issue order; per-acc FP order
            // is unchanged: hh -> hl -> lh).
            #pragma unroll
            for (int mf = 0; mf < 2; mf++)
                #pragma unroll
                for (int nf = 0; nf < 8; nf++)
                    mma16816(acc[mf][nf], ahi[mf], bhi[nf]);
            #pragma unroll
            for (int mf = 0; mf < 2; mf++)
                #pragma unroll
                for (int nf = 0; nf < 8; nf++)
                    mma16816(acc[mf][nf], ahi[mf], blo[nf]);
            #pragma unroll
            for (int mf = 0; mf < 2; mf++)
                #pragma unroll
                for (int nf = 0; nf < 8; nf++)
                    mma16816(acc[mf][nf], alo[mf], bhi[nf]);
        }
        __syncthreads();
    }

    int gg = lane >> 2, t2 = (lane & 3) * 2;
    if (sel < 3) {
        __nv_bfloat16* dhi = (sel == 0) ? g_qhi : (sel == 1) ? g_khi : g_vhi;
        __nv_bfloat16* dlo = (sel == 0) ? g_qlo : (sel == 1) ? g_klo : g_vlo;
        #pragma unroll
        for (int mf = 0; mf < 2; mf++) {
            int row = m0 + wm * 32 + mf * 16 + gg;
            #pragma unroll
            for (int nf = 0; nf < 8; nf++) {
                int col = n0 + wn * 64 + nf * 8 + t2;
                float b0 = bias[col] * bscale, b1 = bias[col + 1] * bscale;
                float v0 = acc[mf][nf][0] + b0, v1 = acc[mf][nf][1] + b1;
                float u0 = acc[mf][nf][2] + b0, u1 = acc[mf][nf][3] + b1;
                __nv_bfloat162 hp, lp;
                hp.x = __float2bfloat16(v0); hp.y = __float2bfloat16(v1);
                lp.x = __float2bfloat16(v0 - __bfloat162float(hp.x));
                lp.y = __float2bfloat16(v1 - __bfloat162float(hp.y));
                *reinterpret_cast<__nv_bfloat162*>(dhi + (size_t)row * HID_ + col) = hp;
                *reinterpret_cast<__nv_bfloat162*>(dlo + (size_t)row * HID_ + col) = lp;
                hp.x = __float2bfloat16(u0); hp.y = __float2bfloat16(u1);
                lp.x = __float2bfloat16(u0 - __bfloat162float(hp.x));
                lp.y = __float2bfloat16(u1 - __bfloat162float(hp.y));
                *reinterpret_cast<__nv_bfloat162*>(dhi + (size_t)(row+8) * HID_ + col) = hp;
                *reinterpret_cast<__nv_bfloat162*>(dlo + (size_t)(row+8) * HID_ + col) = lp;
            }
        }
    } else {
        #pragma unroll
        for (int mf = 0; mf < 2; mf++) {
            int row = m0 + wm * 32 + mf * 16 + gg;
            float* r0 = out_ext + (size_t)row * HID_ + n0 + wn * 64;
            float* r1 = r0 + 8 * HID_;
            #pragma unroll
            for (int nf = 0; nf < 8; nf++) {
                int col = nf * 8 + t2;
                float b0 = bias[n0 + wn * 64 + col]     * bscale;
                float b1 = bias[n0 + wn * 64 + col + 1] * bscale;
                *reinterpret_cast<float2*>(r0 + col) =
                    make_float2(acc[mf][nf][0] + b0, acc[mf][nf][1] + b1);
                *reinterpret_cast<float2*>(r1 + col) =
                    make_float2(acc[mf][nf][2] + b0, acc[mf][nf][3] + b1);
            }
        }
    }
}

__global__ __launch_bounds__(256, 2) void gemm_qkv(
    const float* __restrict__ bq, const float* __restrict__ bk,
    const float* __restrict__ bv)
{
    int sel = blockIdx.z;
    const float* bias = (sel == 0) ? bq : (sel == 1) ? bk : bv;
    float bscale = (sel == 0) ? 0.125f : 1.0f;
    gemm_body(g_ahi + sel * APLANE, g_alo + sel * APLANE,
              g_whi + sel * WPLANE, g_wlo + sel * WPLANE,
              bias, bscale, nullptr, sel);
}

__global__ __launch_bounds__(256, 2) void gemm_out(
    const float* __restrict__ bo, float* __restrict__ out)
{
    gemm_body(g_ahi, g_alo, g_whi + 3 * WPLANE, g_wlo + 3 * WPLANE,
              bo, 1.0f, out, 3);
}

// ------------------------- HMMA flash attention ------------------------------
#define ASTG 32768
#define ATT_SMEM (2*ASTG)

__device__ __forceinline__ uint32_t taddr128(uint32_t base, int row, int ch) {
    return base + row * 128 + ((ch ^ (row & 7)) << 4);
}

__device__ __forceinline__ void att_stage(uint32_t st, int b, int h, int t, int tid) {
    #pragma unroll
    for (int p = 0; p < 8; p++) {
        int idx = tid + p * 256;
        int arr = idx >> 9;
        int row = (idx & 511) >> 3, ch = idx & 7;
        const __nv_bfloat16* src =
            (arr == 0 ? g_khi : arr == 1 ? g_klo : arr == 2 ? g_vhi : g_vlo)
            + (size_t)(b * S_ + t * 64 + row) * HID_ + h * D_ + ch * 8;
        cp16(taddr128(st + arr * 8192, row, ch), src);
    }
}

__global__ __launch_bounds__(256, 2) void attn_mma()
{
    extern __shared__ char raw[];
    uint32_t sb = smem_u32(raw);

    int tid = threadIdx.x, lane = tid & 31, w = tid >> 5;
    int b = blockIdx.y >> 4, h = blockIdx.y & 15;
    int sq0 = blockIdx.x * 128;
    int lrow = lane & 15, lsel = lane >> 4;
    int g = lane >> 2, t4 = lane & 3;

    // Q -> buffer 1 (transient), stage0 -> buffer 0
    #pragma unroll
    for (int p = 0; p < 8; p++) {
        int idx = tid + p * 256;
        int arr = idx >> 10, row = (idx & 1023) >> 3, ch = idx & 7;
        const __nv_bfloat16* src = (arr ? g_qlo : g_qhi)
            + (size_t)(b * S_ + sq0 + row) * HID_ + h * D_ + ch * 8;
        cp16(taddr128(sb + ASTG + arr * 16384, row, ch), src);
    }
    CP_COMMIT();
    att_stage(sb, b, h, 0, tid);
    CP_COMMIT();
    asm volatile("cp.async.wait_group 1;" ::: "memory");   // Q landed
    __syncthreads();

    uint32_t qh_[4][4], ql_[4][4];
    #pragma unroll
    for (int kt = 0; kt < 4; kt++) {
        ldsm4(qh_[kt], taddr128(sb + ASTG,          w * 16 + lrow, 2 * kt + lsel));
        ldsm4(ql_[kt], taddr128(sb + ASTG + 16384,  w * 16 + lrow, 2 * kt + lsel));
    }
    __syncthreads();

    att_stage(sb + ASTG, b, h, 1, tid);
    CP_COMMIT();
    asm volatile("cp.async.wait_group 1;" ::: "memory");   // stage0 landed
    __syncthreads();

    float oc[8][4];
    #pragma unroll
    for (int n = 0; n < 8; n++)
        #pragma unroll
        for (int c = 0; c < 4; c++) oc[n][c] = 0.f;
    float l0 = 0.f, l1 = 0.f;

    for (int t = 0; t < S_ / 64; t++) {
        if (t > 0) {
            if (t + 1 < S_ / 64)
                att_stage(sb + (uint32_t)((t + 1) & 1) * ASTG, b, h, t + 1, tid);
            CP_COMMIT();
            asm volatile("cp.async.wait_group 1;" ::: "memory");
            __syncthreads();
        }
        uint32_t buf = sb + (uint32_t)(t & 1) * ASTG;

        float sc[8][4];
        #pragma unroll
        for (int n = 0; n < 8; n++)
            #pragma unroll
            for (int c = 0; c < 4; c++) sc[n][c] = 0.f;

        #pragma unroll
        for (int kt = 0; kt < 4; kt++) {
            uint32_t bh[8][2], bl[8][2], tt[4];
            #pragma unroll
            for (int j = 0; j < 4; j++) {
                ldsm4(tt, taddr128(buf, j * 16 + lrow, 2 * kt + lsel));
                bh[2*j][0]=tt[0]; bh[2*j+1][0]=tt[1]; bh[2*j][1]=tt[2]; bh[2*j+1][1]=tt[3];
                ldsm4(tt, taddr128(buf + 8192, j * 16 + lrow, 2 * kt + lsel));
                bl[2*j][0]=tt[0]; bl[2*j+1][0]=tt[1]; bl[2*j][1]=tt[2]; bl[2*j+1][1]=tt[3];
            }
            // product-kind outermost: 8 independent MMAs between acc reuses
            #pragma unroll
            for (int n = 0; n < 8; n++) mma16816(sc[n], qh_[kt], bh[n]);
            #pragma unroll
            for (int n = 0; n < 8; n++) mma16816(sc[n], qh_[kt], bl[n]);
            #pragma unroll
            for (int n = 0; n < 8; n++) mma16816(sc[n], ql_[kt], bh[n]);
        }

        size_t mrow = ((size_t)b * S_ + sq0 + w * 16 + g) * (S_ / 32) + 2 * t;
        uint32_t w00 = g_mb[mrow], w01 = g_mb[mrow + 1];
        uint32_t w10 = g_mb[mrow + 8 * (S_ / 32)], w11 = g_mb[mrow + 8 * (S_ / 32) + 1];
        #pragma unroll
        for (int j = 0; j < 8; j++) {
            int bit = (8 * j + 2 * t4) & 31;
            uint32_t wa = (j < 4) ? w00 : w01;
            uint32_t wb = (j < 4) ? w10 : w11;
            if (!((wa >> bit) & 1))       sc[j][0] = -1.0e9f;
            if (!((wa >> (bit + 1)) & 1)) sc[j][1] = -1.0e9f;
            if (!((wb >> bit) & 1))       sc[j][2] = -1.0e9f;
            if (!((wb >> (bit + 1)) & 1)) sc[j][3] = -1.0e9f;
        }

        #pragma unroll
        for (int j = 0; j < 8; j++) {
            sc[j][0] = __expf(sc[j][0]); l0 += sc[j][0];
            sc[j][1] = __expf(sc[j][1]); l0 += sc[j][1];
            sc[j][2] = __expf(sc[j][2]); l1 += sc[j][2];
            sc[j][3] = __expf(sc[j][3]); l1 += sc[j][3];
        }

        uint32_t ph[4][4], pl[4][4];
        #pragma unroll
        for (int j2 = 0; j2 < 4; j2++) {
            ph[j2][0] = packbf(sc[2*j2][0],   sc[2*j2][1]);
            ph[j2][1] = packbf(sc[2*j2][2],   sc[2*j2][3]);
            ph[j2][2] = packbf(sc[2*j2+1][0], sc[2*j2+1][1]);
            ph[j2][3] = packbf(sc[2*j2+1][2], sc[2*j2+1][3]);
            pl[j2][0] = packbf(bfres(sc[2*j2][0]),   bfres(sc[2*j2][1]));
            pl[j2][1] = packbf(bfres(sc[2*j2][2]),   bfres(sc[2*j2][3]));
            pl[j2][2] = packbf(bfres(sc[2*j2+1][0]), bfres(sc[2*j2+1][1]));
            pl[j2][3] = packbf(bfres(sc[2*j2+1][2]), bfres(sc[2*j2+1][3]));
        }

        #pragma unroll
        for (int j2 = 0; j2 < 4; j2++) {
            uint32_t vh[8][2], vl[8][2], tt[4];
            #pragma unroll
            for (int np = 0; np < 4; np++) {
                ldsm4t(tt, taddr128(buf + 16384, j2 * 16 + lrow, 2 * np + lsel));
                vh[2*np][0]=tt[0]; vh[2*np][1]=tt[1]; vh[2*np+1][0]=tt[2]; vh[2*np+1][1]=tt[3];
                ldsm4t(tt, taddr128(buf + 24576, j2 * 16 + lrow, 2 * np + lsel));
                vl[2*np][0]=tt[0]; vl[2*np][1]=tt[1]; vl[2*np+1][0]=tt[2]; vl[2*np+1][1]=tt[3];
            }
            #pragma unroll
            for (int n = 0; n < 8; n++) mma16816(oc[n], ph[j2], vh[n]);
            #pragma unroll
            for (int n = 0; n < 8; n++) mma16816(oc[n], ph[j2], vl[n]);
            #pragma unroll
            for (int n = 0; n < 8; n++) mma16816(oc[n], pl[j2], vh[n]);
        }
        __syncthreads();
    }

    l0 += __shfl_xor_sync(0xffffffffu, l0, 1);
    l0 += __shfl_xor_sync(0xffffffffu, l0, 2);
    l1 += __shfl_xor_sync(0xffffffffu, l1, 1);
    l1 += __shfl_xor_sync(0xffffffffu, l1, 2);
    float inv0 = 1.f / l0, inv1 = 1.f / l1;
    size_t base0 = (size_t)(b * S_ + sq0 + w * 16 + g) * HID_ + h * D_;
    size_t base1 = base0 + (size_t)8 * HID_;
    #pragma unroll
    for (int j = 0; j < 8; j++) {
        int col = 8 * j + 2 * t4;
        float v0 = oc[j][0] * inv0, v1 = oc[j][1] * inv0;
        float u0 = oc[j][2] * inv1, u1 = oc[j][3] * inv1;
        __nv_bfloat162 hp, lp;
        hp.x = __float2bfloat16(v0); hp.y = __float2bfloat16(v1);
        lp.x = __float2bfloat16(v0 - __bfloat162float(hp.x));
        lp.y = __float2bfloat16(v1 - __bfloat162float(hp.y));
        *reinterpret_cast<__nv_bfloat162*>(g_ahi + base0 + col) = hp;
        *reinterpret_cast<__nv_bfloat162*>(g_alo + base0 + col) = lp;
        hp.x = __float2bfloat16(u0); hp.y = __float2bfloat16(u1);
        lp.x = __float2bfloat16(u0 - __bfloat162float(hp.x));
        lp.y = __float2bfloat16(u1 - __bfloat162float(hp.y));
        *reinterpret_cast<__nv_bfloat162*>(g_ahi + base1 + col) = hp;
        *reinterpret_cast<__nv_bfloat162*>(g_alo + base1 + col) = lp;
    }
}

// ------------------------- launch --------------------------------------------
extern "C" void kernel_launch(void* const* d_in, const int* in_sizes, int n_in,
                              void* d_out, int out_size)
{
    const float* qh  = (const float*)d_in[0];
    const float* kh  = (const float*)d_in[1];
    const float* vh  = (const float*)d_in[2];
    const void*  mask = d_in[3];
    const float* wq  = (const float*)d_in[4];
    const float* bq  = (const float*)d_in[5];
    const float* wk  = (const float*)d_in[6];
    const float* bk  = (const float*)d_in[7];
    const float* wv  = (const float*)d_in[8];
    const float* bv  = (const float*)d_in[9];
    const float* wo  = (const float*)d_in[10];
    const float* bo  = (const float*)d_in[11];
    float* out = (float*)d_out;

    cudaFuncSetAttribute(gemm_qkv, cudaFuncAttributeMaxDynamicSharedMemorySize, 2*STG);
    cudaFuncSetAttribute(gemm_out, cudaFuncAttributeMaxDynamicSharedMemorySize, 2*STG);
    cudaFuncSetAttribute(attn_mma, cudaFuncAttributeMaxDynamicSharedMemorySize, ATT_SMEM);

    detect_mask_kernel<<<1, 256>>>((const unsigned int*)mask);
    pack_mask<<<(B_*S_*(S_/32))/1024, 256>>>(mask);

    split3_kernel<<<dim3((NROWS_*HID_/4)/1024, 3), 256>>>(
        (const float4*)qh, (const float4*)kh, (const float4*)vh);
    prep_w4<<<dim3(HID_/256, HID_, 4), 256>>>(wq, wk, wv, wo);
    gemm_qkv<<<dim3(NROWS_/128, HID_/128, 3), 256, 2*STG>>>(bq, bk, bv);

    attn_mma<<<dim3(S_/128, B_*H_), 256, ATT_SMEM>>>();

    gemm_out<<<dim3(NROWS_/128, HID_/128), 256, 2*STG>>>(bo, out);
}

// round 10
// speedup vs baseline: 1.4194x; 1.4194x over previous
#include <cuda_runtime.h>
#include <cuda_fp16.h>
#include <cstdint>

#define B_ 4
#define S_ 2048
#define H_ 16
#define D_ 64
#define HID_ 1024
#define NROWS_ (B_*S_)
#define APLANE ((size_t)NROWS_*HID_)
#define WPLANE ((size_t)HID_*HID_)

// ------------------------- device scratch (no allocs) -----------------------
__device__ __half g_qhi[APLANE];   // Q split hi/lo (fp16), pre-scaled 1/8
__device__ __half g_qlo[APLANE];
__device__ __half g_k[APLANE];     // K single fp16
__device__ __half g_v[APLANE];     // V single fp16
__device__ __half g_ahi[3*APLANE]; // GEMM A planes hi (q/k/v inputs; plane0 reused for attn out)
__device__ __half g_alo[3*APLANE];
__device__ __half g_w[4*WPLANE];   // weights single fp16 [N][K]; plane3 = wo
__device__ uint32_t g_mb[(size_t)B_*S_*(S_/32)];
__device__ int g_mask_mode;

// ------------------------- helpers ------------------------------------------
__device__ __forceinline__ uint32_t smem_u32(const void* p) {
    uint32_t a;
    asm("{ .reg .u64 t; cvta.to.shared.u64 t, %1; cvt.u32.u64 %0, t; }"
        : "=r"(a) : "l"(p));
    return a;
}
__device__ __forceinline__ void cp16(uint32_t dst, const void* src) {
    asm volatile("cp.async.cg.shared.global [%0], [%1], 16;\n" :: "r"(dst), "l"(src));
}
#define CP_COMMIT() asm volatile("cp.async.commit_group;\n" ::: "memory")

__device__ __forceinline__ void ldsm4(uint32_t* r, uint32_t addr) {
    asm volatile("ldmatrix.sync.aligned.m8n8.x4.shared.b16 {%0,%1,%2,%3}, [%4];"
        : "=r"(r[0]), "=r"(r[1]), "=r"(r[2]), "=r"(r[3]) : "r"(addr));
}
__device__ __forceinline__ void ldsm4t(uint32_t* r, uint32_t addr) {
    asm volatile("ldmatrix.sync.aligned.m8n8.x4.trans.shared.b16 {%0,%1,%2,%3}, [%4];"
        : "=r"(r[0]), "=r"(r[1]), "=r"(r[2]), "=r"(r[3]) : "r"(addr));
}
// fp16 MMA, fp32 accumulate
__device__ __forceinline__ void mma16816(float* d, const uint32_t* a, const uint32_t* b) {
    asm volatile("mma.sync.aligned.m16n8k16.row.col.f32.f16.f16.f32 "
        "{%0,%1,%2,%3}, {%4,%5,%6,%7}, {%8,%9}, {%0,%1,%2,%3};"
        : "+f"(d[0]), "+f"(d[1]), "+f"(d[2]), "+f"(d[3])
        : "r"(a[0]), "r"(a[1]), "r"(a[2]), "r"(a[3]), "r"(b[0]), "r"(b[1]));
}
// pack(e0 -> low half, e1 -> high half) as fp16x2
__device__ __forceinline__ uint32_t packh2(float e0, float e1) {
    uint32_t d;
    asm("cvt.rn.f16x2.f32 %0, %1, %2;" : "=r"(d) : "f"(e1), "f"(e0));
    return d;
}
__device__ __forceinline__ float h16res(float x) {
    return x - __half2float(__float2half_rn(x));
}

// ------------------------- mask detect + pack --------------------------------
__global__ void detect_mask_kernel(const unsigned int* __restrict__ m) {
    __shared__ int sF, sO;
    if (threadIdx.x == 0) { sF = 0; sO = 0; }
    __syncthreads();
    bool f = false, o = false;
    for (int i = threadIdx.x; i < 2048; i += 256) {
        unsigned int w = m[i];
        if (w == 0u || w == 1u) continue;
        if (w == 0x3f800000u) f = true; else o = true;
    }
    if (f) sF = 1;
    if (o) sO = 1;
    __syncthreads();
    if (threadIdx.x == 0) g_mask_mode = sO ? 1 : (sF ? 2 : 0);
}

__global__ __launch_bounds__(256) void pack_mask(const void* __restrict__ mask) {
    int mode = g_mask_mode;
    #pragma unroll
    for (int p = 0; p < 4; p++) {
        int widx = blockIdx.x * 1024 + p * 256 + threadIdx.x;
        uint32_t bits = 0;
        if (mode == 1) {
            const uchar4* pp = (const uchar4*)mask + (size_t)widx * 8;
            #pragma unroll
            for (int q = 0; q < 8; q++) {
                uchar4 v = pp[q];
                bits |= (uint32_t)(v.x != 0) << (4*q)
                     |  (uint32_t)(v.y != 0) << (4*q+1)
                     |  (uint32_t)(v.z != 0) << (4*q+2)
                     |  (uint32_t)(v.w != 0) << (4*q+3);
            }
        } else if (mode == 2) {
            const float4* pp = (const float4*)mask + (size_t)widx * 8;
            #pragma unroll
            for (int q = 0; q < 8; q++) {
                float4 v = pp[q];
                bits |= (uint32_t)(v.x != 0.f) << (4*q)
                     |  (uint32_t)(v.y != 0.f) << (4*q+1)
                     |  (uint32_t)(v.z != 0.f) << (4*q+2)
                     |  (uint32_t)(v.w != 0.f) << (4*q+3);
            }
        } else {
            const int4* pp = (const int4*)mask + (size_t)widx * 8;
            #pragma unroll
            for (int q = 0; q < 8; q++) {
                int4 v = pp[q];
                bits |= (uint32_t)(v.x != 0) << (4*q)
                     |  (uint32_t)(v.y != 0) << (4*q+1)
                     |  (uint32_t)(v.z != 0) << (4*q+2)
                     |  (uint32_t)(v.w != 0) << (4*q+3);
            }
        }
        g_mb[widx] = bits;
    }
}

// ------------------------- prep kernels --------------------------------------
__global__ __launch_bounds__(256) void split3_kernel(
    const float4* __restrict__ x0, const float4* __restrict__ x1,
    const float4* __restrict__ x2)
{
    int pl = blockIdx.y;
    const float4* __restrict__ src = (pl == 0) ? x0 : (pl == 1) ? x1 : x2;
    __half2* hi = reinterpret_cast<__half2*>(g_ahi + pl * APLANE);
    __half2* lo = reinterpret_cast<__half2*>(g_alo + pl * APLANE);
    #pragma unroll
    for (int p = 0; p < 4; p++) {
        size_t i = (size_t)blockIdx.x * 1024 + p * 256 + threadIdx.x;
        float4 v = src[i];
        __half h0 = __float2half_rn(v.x), h1 = __float2half_rn(v.y);
        __half h2 = __float2half_rn(v.z), h3 = __float2half_rn(v.w);
        __half2 a, b;
        a.x = h0; a.y = h1; b.x = h2; b.y = h3;
        hi[i*2] = a; hi[i*2+1] = b;
        a.x = __float2half_rn(v.x - __half2float(h0));
        a.y = __float2half_rn(v.y - __half2float(h1));
        b.x = __float2half_rn(v.z - __half2float(h2));
        b.y = __float2half_rn(v.w - __half2float(h3));
        lo[i*2] = a; lo[i*2+1] = b;
    }
}

// 4 weight planes, single fp16: 0..2 = wq/wk/wv, 3 = wo transpose
__global__ __launch_bounds__(256) void prep_w4(
    const float* __restrict__ w0, const float* __restrict__ w1,
    const float* __restrict__ w2, const float* __restrict__ w3)
{
    int pl = blockIdx.z;
    int k = blockIdx.x * 256 + threadIdx.x;
    int n = blockIdx.y;
    float v;
    if (pl < 3) {
        const float* __restrict__ w = (pl == 0) ? w0 : (pl == 1) ? w1 : w2;
        float scale = (pl == 0) ? 0.125f : 1.0f;
        int h = n >> 6, d = n & 63;
        v = w[((size_t)h * HID_ + k) * D_ + d] * scale;
    } else {
        v = w3[(size_t)k * HID_ + n];
    }
    g_w[pl * WPLANE + (size_t)n * HID_ + k] = __float2half_rn(v);
}

// ------------------------- HMMA GEMM (fp16, 2-product) -----------------------
// C = (Ahi+Alo) x W^T + bias; A split fp16 hi/lo, W single fp16.
// Stage: Ahi 8K + Alo 8K + W 8K = 24KB; 2 stages = 48KB -> 2 CTAs/SM.
#define STG 24576
#define OFF_ALO 8192
#define OFF_W   16384

__device__ __forceinline__ uint32_t taddr(uint32_t base, int row, int chunk) {
    return base + row * 64 + ((chunk ^ ((row >> 1) & 3)) << 4);
}

__device__ __forceinline__ void load_tile(uint32_t dstbase,
    const __half* __restrict__ src, int row0, int k0, int tid)
{
    #pragma unroll
    for (int p = 0; p < 2; p++) {
        int idx = tid + p * 256;
        int row = idx >> 2, ch = idx & 3;
        cp16(taddr(dstbase, row, ch),
             src + (size_t)(row0 + row) * HID_ + k0 + ch * 8);
    }
}

__device__ __forceinline__ void gemm_body(
    const __half* __restrict__ Ahi, const __half* __restrict__ Alo,
    const __half* __restrict__ W,
    const float* __restrict__ bias, float bscale,
    float* __restrict__ out_ext, int sel)
{
    extern __shared__ char raw[];
    uint32_t sb = smem_u32(raw);

    int tid = threadIdx.x, lane = tid & 31, wid = tid >> 5;
    int wm = wid & 3, wn = wid >> 2;
    int m0 = blockIdx.x * 128, n0 = blockIdx.y * 128;
    int lrow = lane & 15, lsel = lane >> 4;

    float acc[2][8][4];
    #pragma unroll
    for (int a = 0; a < 2; a++)
        #pragma unroll
        for (int b = 0; b < 8; b++)
            #pragma unroll
            for (int c = 0; c < 4; c++) acc[a][b][c] = 0.f;

    load_tile(sb,           Ahi, m0, 0, tid);
    load_tile(sb + OFF_ALO, Alo, m0, 0, tid);
    load_tile(sb + OFF_W,   W,   n0, 0, tid);
    CP_COMMIT();

    const int NST = HID_ / 32;
    for (int i = 0; i < NST; i++) {
        if (i + 1 < NST) {
            uint32_t nb = sb + (uint32_t)((i + 1) & 1) * STG;
            int k0 = (i + 1) * 32;
            load_tile(nb,           Ahi, m0, k0, tid);
            load_tile(nb + OFF_ALO, Alo, m0, k0, tid);
            load_tile(nb + OFF_W,   W,   n0, k0, tid);
            CP_COMMIT();
            asm volatile("cp.async.wait_group 1;" ::: "memory");
        } else {
            asm volatile("cp.async.wait_group 0;" ::: "memory");
        }
        __syncthreads();

        uint32_t buf = sb + (uint32_t)(i & 1) * STG;
        #pragma unroll
        for (int kk = 0; kk < 2; kk++) {
            int chunk = (kk << 1) + lsel;
            uint32_t ahi[2][4], alo[2][4];
            #pragma unroll
            for (int mf = 0; mf < 2; mf++) {
                int row = wm * 32 + mf * 16 + lrow;
                uint32_t ad = taddr(buf, row, chunk);
                ldsm4(ahi[mf], ad);
                ldsm4(alo[mf], ad + OFF_ALO);
            }
            uint32_t wfr[8][2];
            #pragma unroll
            for (int j = 0; j < 4; j++) {
                int row = wn * 64 + j * 16 + lrow;
                uint32_t t4[4];
                ldsm4(t4, taddr(buf + OFF_W, row, chunk));
                wfr[2*j][0] = t4[0]; wfr[2*j+1][0] = t4[1];
                wfr[2*j][1] = t4[2]; wfr[2*j+1][1] = t4[3];
            }
            #pragma unroll
            for (int mf = 0; mf < 2; mf++)
                #pragma unroll
                for (int nf = 0; nf < 8; nf++)
                    mma16816(acc[mf][nf], ahi[mf], wfr[nf]);
            #pragma unroll
            for (int mf = 0; mf < 2; mf++)
                #pragma unroll
                for (int nf = 0; nf < 8; nf++)
                    mma16816(acc[mf][nf], alo[mf], wfr[nf]);
        }
        __syncthreads();
    }

    int gg = lane >> 2, t2 = (lane & 3) * 2;
    if (sel == 0) {
        // Q: split fp16 hi/lo
        #pragma unroll
        for (int mf = 0; mf < 2; mf++) {
            int row = m0 + wm * 32 + mf * 16 + gg;
            #pragma unroll
            for (int nf = 0; nf < 8; nf++) {
                int col = n0 + wn * 64 + nf * 8 + t2;
                float b0 = bias[col] * bscale, b1 = bias[col + 1] * bscale;
                float v0 = acc[mf][nf][0] + b0, v1 = acc[mf][nf][1] + b1;
                float u0 = acc[mf][nf][2] + b0, u1 = acc[mf][nf][3] + b1;
                __half2 hp, lp;
                hp.x = __float2half_rn(v0); hp.y = __float2half_rn(v1);
                lp.x = __float2half_rn(v0 - __half2float(hp.x));
                lp.y = __float2half_rn(v1 - __half2float(hp.y));
                *reinterpret_cast<__half2*>(g_qhi + (size_t)row * HID_ + col) = hp;
                *reinterpret_cast<__half2*>(g_qlo + (size_t)row * HID_ + col) = lp;
                hp.x = __float2half_rn(u0); hp.y = __float2half_rn(u1);
                lp.x = __float2half_rn(u0 - __half2float(hp.x));
                lp.y = __float2half_rn(u1 - __half2float(hp.y));
                *reinterpret_cast<__half2*>(g_qhi + (size_t)(row+8) * HID_ + col) = hp;
                *reinterpret_cast<__half2*>(g_qlo + (size_t)(row+8) * HID_ + col) = lp;
            }
        }
    } else if (sel < 3) {
        // K/V: single fp16
        __half* dst = (sel == 1) ? g_k : g_v;
        #pragma unroll
        for (int mf = 0; mf < 2; mf++) {
            int row = m0 + wm * 32 + mf * 16 + gg;
            #pragma unroll
            for (int nf = 0; nf < 8; nf++) {
                int col = n0 + wn * 64 + nf * 8 + t2;
                float b0 = bias[col] * bscale, b1 = bias[col + 1] * bscale;
                __half2 hp;
                hp.x = __float2half_rn(acc[mf][nf][0] + b0);
                hp.y = __float2half_rn(acc[mf][nf][1] + b1);
                *reinterpret_cast<__half2*>(dst + (size_t)row * HID_ + col) = hp;
                hp.x = __float2half_rn(acc[mf][nf][2] + b0);
                hp.y = __float2half_rn(acc[mf][nf][3] + b1);
                *reinterpret_cast<__half2*>(dst + (size_t)(row+8) * HID_ + col) = hp;
            }
        }
    } else {
        #pragma unroll
        for (int mf = 0; mf < 2; mf++) {
            int row = m0 + wm * 32 + mf * 16 + gg;
            float* r0 = out_ext + (size_t)row * HID_ + n0 + wn * 64;
            float* r1 = r0 + 8 * HID_;
            #pragma unroll
            for (int nf = 0; nf < 8; nf++) {
                int col = nf * 8 + t2;
                float b0 = bias[n0 + wn * 64 + col]     * bscale;
                float b1 = bias[n0 + wn * 64 + col + 1] * bscale;
                *reinterpret_cast<float2*>(r0 + col) =
                    make_float2(acc[mf][nf][0] + b0, acc[mf][nf][1] + b1);
                *reinterpret_cast<float2*>(r1 + col) =
                    make_float2(acc[mf][nf][2] + b0, acc[mf][nf][3] + b1);
            }
        }
    }
}

__global__ __launch_bounds__(256, 2) void gemm_qkv(
    const float* __restrict__ bq, const float* __restrict__ bk,
    const float* __restrict__ bv)
{
    int sel = blockIdx.z;
    const float* bias = (sel == 0) ? bq : (sel == 1) ? bk : bv;
    float bscale = (sel == 0) ? 0.125f : 1.0f;
    gemm_body(g_ahi + sel * APLANE, g_alo + sel * APLANE,
              g_w + sel * WPLANE, bias, bscale, nullptr, sel);
}

__global__ __launch_bounds__(256, 2) void gemm_out(
    const float* __restrict__ bo, float* __restrict__ out)
{
    gemm_body(g_ahi, g_alo, g_w + 3 * WPLANE, bo, 1.0f, out, 3);
}

// ------------------------- HMMA flash attention (fp16, 2-product) ------------
// QK: Q split fp16 hi/lo (registers), K single fp16 (streamed).
// PV: P split fp16 hi/lo (registers), V single fp16 (streamed).
// Stage = K 8KB + V 8KB = 16KB; 2 stages = 32KB. Q staged through both buffers.
#define ASTG 16384
#define ATT_SMEM (2*ASTG)

__device__ __forceinline__ uint32_t taddr128(uint32_t base, int row, int ch) {
    return base + row * 128 + ((ch ^ (row & 7)) << 4);
}

__device__ __forceinline__ void att_stage(uint32_t st, int b, int h, int t, int tid) {
    #pragma unroll
    for (int p = 0; p < 4; p++) {
        int idx = tid + p * 256;
        int arr = idx >> 9;            // 0 = K, 1 = V
        int row = (idx & 511) >> 3, ch = idx & 7;
        const __half* src = (arr ? g_v : g_k)
            + (size_t)(b * S_ + t * 64 + row) * HID_ + h * D_ + ch * 8;
        cp16(taddr128(st + arr * 8192, row, ch), src);
    }
}

__global__ __launch_bounds__(256, 2) void attn_mma()
{
    extern __shared__ char raw[];
    uint32_t sb = smem_u32(raw);

    int tid = threadIdx.x, lane = tid & 31, w = tid >> 5;
    int b = blockIdx.y >> 4, h = blockIdx.y & 15;
    int sq0 = blockIdx.x * 128;
    int lrow = lane & 15, lsel = lane >> 4;
    int g = lane >> 2, t4 = lane & 3;

    // Q hi -> buf0, Q lo -> buf1 (transient)
    #pragma unroll
    for (int p = 0; p < 8; p++) {
        int idx = tid + p * 256;
        int arr = idx >> 10, row = (idx & 1023) >> 3, ch = idx & 7;
        const __half* src = (arr ? g_qlo : g_qhi)
            + (size_t)(b * S_ + sq0 + row) * HID_ + h * D_ + ch * 8;
        cp16(taddr128(sb + (uint32_t)arr * ASTG, row, ch), src);
    }
    CP_COMMIT();
    asm volatile("cp.async.wait_group 0;" ::: "memory");
    __syncthreads();

    uint32_t qh_[4][4], ql_[4][4];
    #pragma unroll
    for (int kt = 0; kt < 4; kt++) {
        ldsm4(qh_[kt], taddr128(sb,         w * 16 + lrow, 2 * kt + lsel));
        ldsm4(ql_[kt], taddr128(sb + ASTG,  w * 16 + lrow, 2 * kt + lsel));
    }
    __syncthreads();

    att_stage(sb, b, h, 0, tid);
    CP_COMMIT();
    att_stage(sb + ASTG, b, h, 1, tid);
    CP_COMMIT();
    asm volatile("cp.async.wait_group 1;" ::: "memory");   // stage0 landed
    __syncthreads();

    float oc[8][4];
    #pragma unroll
    for (int n = 0; n < 8; n++)
        #pragma unroll
        for (int c = 0; c < 4; c++) oc[n][c] = 0.f;
    float l0 = 0.f, l1 = 0.f;

    for (int t = 0; t < S_ / 64; t++) {
        if (t > 0) {
            if (t + 1 < S_ / 64)
                att_stage(sb + (uint32_t)((t + 1) & 1) * ASTG, b, h, t + 1, tid);
            CP_COMMIT();
            asm volatile("cp.async.wait_group 1;" ::: "memory");
            __syncthreads();
        }
        uint32_t buf = sb + (uint32_t)(t & 1) * ASTG;

        float sc[8][4];
        #pragma unroll
        for (int n = 0; n < 8; n++)
            #pragma unroll
            for (int c = 0; c < 4; c++) sc[n][c] = 0.f;

        #pragma unroll
        for (int kt = 0; kt < 4; kt++) {
            uint32_t kf[8][2], tt[4];
            #pragma unroll
            for (int j = 0; j < 4; j++) {
                ldsm4(tt, taddr128(buf, j * 16 + lrow, 2 * kt + lsel));
                kf[2*j][0]=tt[0]; kf[2*j+1][0]=tt[1]; kf[2*j][1]=tt[2]; kf[2*j+1][1]=tt[3];
            }
            #pragma unroll
            for (int n = 0; n < 8; n++) mma16816(sc[n], qh_[kt], kf[n]);
            #pragma unroll
            for (int n = 0; n < 8; n++) mma16816(sc[n], ql_[kt], kf[n]);
        }

        size_t mrow = ((size_t)b * S_ + sq0 + w * 16 + g) * (S_ / 32) + 2 * t;
        uint32_t w00 = g_mb[mrow], w01 = g_mb[mrow + 1];
        uint32_t w10 = g_mb[mrow + 8 * (S_ / 32)], w11 = g_mb[mrow + 8 * (S_ / 32) + 1];
        #pragma unroll
        for (int j = 0; j < 8; j++) {
            int bit = (8 * j + 2 * t4) & 31;
            uint32_t wa = (j < 4) ? w00 : w01;
            uint32_t wb = (j < 4) ? w10 : w11;
            if (!((wa >> bit) & 1))       sc[j][0] = -1.0e9f;
            if (!((wa >> (bit + 1)) & 1)) sc[j][1] = -1.0e9f;
            if (!((wb >> bit) & 1))       sc[j][2] = -1.0e9f;
            if (!((wb >> (bit + 1)) & 1)) sc[j][3] = -1.0e9f;
        }

        // fixed-shift softmax numerator (scores bounded; masked -> exactly 0)
        #pragma unroll
        for (int j = 0; j < 8; j++) {
            sc[j][0] = __expf(sc[j][0]); l0 += sc[j][0];
            sc[j][1] = __expf(sc[j][1]); l0 += sc[j][1];
            sc[j][2] = __expf(sc[j][2]); l1 += sc[j][2];
            sc[j][3] = __expf(sc[j][3]); l1 += sc[j][3];
        }

        // P -> fp16 hi/lo A-fragments
        uint32_t ph[4][4], pl[4][4];
        #pragma unroll
        for (int j2 = 0; j2 < 4; j2++) {
            ph[j2][0] = packh2(sc[2*j2][0],   sc[2*j2][1]);
            ph[j2][1] = packh2(sc[2*j2][2],   sc[2*j2][3]);
            ph[j2][2] = packh2(sc[2*j2+1][0], sc[2*j2+1][1]);
            ph[j2][3] = packh2(sc[2*j2+1][2], sc[2*j2+1][3]);
            pl[j2][0] = packh2(h16res(sc[2*j2][0]),   h16res(sc[2*j2][1]));
            pl[j2][1] = packh2(h16res(sc[2*j2][2]),   h16res(sc[2*j2][3]));
            pl[j2][2] = packh2(h16res(sc[2*j2+1][0]), h16res(sc[2*j2+1][1]));
            pl[j2][3] = packh2(h16res(sc[2*j2+1][2]), h16res(sc[2*j2+1][3]));
        }

        #pragma unroll
        for (int j2 = 0; j2 < 4; j2++) {
            uint32_t vf[8][2], tt[4];
            #pragma unroll
            for (int np = 0; np < 4; np++) {
                ldsm4t(tt, taddr128(buf + 8192, j2 * 16 + lrow, 2 * np + lsel));
                vf[2*np][0]=tt[0]; vf[2*np][1]=tt[1]; vf[2*np+1][0]=tt[2]; vf[2*np+1][1]=tt[3];
            }
            #pragma unroll
            for (int n = 0; n < 8; n++) mma16816(oc[n], ph[j2], vf[n]);
            #pragma unroll
            for (int n = 0; n < 8; n++) mma16816(oc[n], pl[j2], vf[n]);
        }
        __syncthreads();
    }

    l0 += __shfl_xor_sync(0xffffffffu, l0, 1);
    l0 += __shfl_xor_sync(0xffffffffu, l0, 2);
    l1 += __shfl_xor_sync(0xffffffffu, l1, 1);
    l1 += __shfl_xor_sync(0xffffffffu, l1, 2);
    float inv0 = 1.f / l0, inv1 = 1.f / l1;
    size_t base0 = (size_t)(b * S_ + sq0 + w * 16 + g) * HID_ + h * D_;
    size_t base1 = base0 + (size_t)8 * HID_;
    #pragma unroll
    for (int j = 0; j < 8; j++) {
        int col = 8 * j + 2 * t4;
        float v0 = oc[j][0] * inv0, v1 = oc[j][1] * inv0;
        float u0 = oc[j][2] * inv1, u1 = oc[j][3] * inv1;
        __half2 hp, lp;
        hp.x = __float2half_rn(v0); hp.y = __float2half_rn(v1);
        lp.x = __float2half_rn(v0 - __half2float(hp.x));
        lp.y = __float2half_rn(v1 - __half2float(hp.y));
        *reinterpret_cast<__half2*>(g_ahi + base0 + col) = hp;
        *reinterpret_cast<__half2*>(g_alo + base0 + col) = lp;
        hp.x = __float2half_rn(u0); hp.y = __float2half_rn(u1);
        lp.x = __float2half_rn(u0 - __half2float(hp.x));
        lp.y = __float2half_rn(u1 - __half2float(hp.y));
        *reinterpret_cast<__half2*>(g_ahi + base1 + col) = hp;
        *reinterpret_cast<__half2*>(g_alo + base1 + col) = lp;
    }
}

// ------------------------- launch --------------------------------------------
extern "C" void kernel_launch(void* const* d_in, const int* in_sizes, int n_in,
                              void* d_out, int out_size)
{
    const float* qh  = (const float*)d_in[0];
    const float* kh  = (const float*)d_in[1];
    const float* vh  = (const float*)d_in[2];
    const void*  mask = d_in[3];
    const float* wq  = (const float*)d_in[4];
    const float* bq  = (const float*)d_in[5];
    const float* wk  = (const float*)d_in[6];
    const float* bk  = (const float*)d_in[7];
    const float* wv  = (const float*)d_in[8];
    const float* bv  = (const float*)d_in[9];
    const float* wo  = (const float*)d_in[10];
    const float* bo  = (const float*)d_in[11];
    float* out = (float*)d_out;

    cudaFuncSetAttribute(gemm_qkv, cudaFuncAttributeMaxDynamicSharedMemorySize, 2*STG);
    cudaFuncSetAttribute(gemm_out, cudaFuncAttributeMaxDynamicSharedMemorySize, 2*STG);
    cudaFuncSetAttribute(attn_mma, cudaFuncAttributeMaxDynamicSharedMemorySize, ATT_SMEM);

    detect_mask_kernel<<<1, 256>>>((const unsigned int*)mask);
    pack_mask<<<(B_*S_*(S_/32))/1024, 256>>>(mask);

    split3_kernel<<<dim3((NROWS_*HID_/4)/1024, 3), 256>>>(
        (const float4*)qh, (const float4*)kh, (const float4*)vh);
    prep_w4<<<dim3(HID_/256, HID_, 4), 256>>>(wq, wk, wv, wo);
    gemm_qkv<<<dim3(NROWS_/128, HID_/128, 3), 256, 2*STG>>>(bq, bk, bv);

    attn_mma<<<dim3(S_/128, B_*H_), 256, ATT_SMEM>>>();

    gemm_out<<<dim3(NROWS_/128, HID_/128), 256, 2*STG>>>(bo, out);
}

// round 11
// speedup vs baseline: 2.3107x; 1.6279x over previous
#include <cuda_runtime.h>
#include <cuda_fp16.h>
#include <cstdint>

#define B_ 4
#define S_ 2048
#define H_ 16
#define D_ 64
#define HID_ 1024
#define NROWS_ (B_*S_)
#define APLANE ((size_t)NROWS_*HID_)
#define WPLANE ((size_t)HID_*HID_)

// ------------------------- device scratch (no allocs) -----------------------
__device__ __half g_q[APLANE];     // Q fp16, pre-scaled 1/8
__device__ __half g_k[APLANE];     // K fp16
__device__ __half g_v[APLANE];     // V fp16
__device__ __half g_a[3*APLANE];   // GEMM A planes (q/k/v inputs; plane0 reused attn out)
__device__ __half g_w[4*WPLANE];   // weights fp16 [N][K]; plane3 = wo
__device__ uint32_t g_mb[(size_t)B_*S_*(S_/32)];
__device__ int g_mask_mode;

// ------------------------- helpers ------------------------------------------
__device__ __forceinline__ uint32_t smem_u32(const void* p) {
    uint32_t a;
    asm("{ .reg .u64 t; cvta.to.shared.u64 t, %1; cvt.u32.u64 %0, t; }"
        : "=r"(a) : "l"(p));
    return a;
}
__device__ __forceinline__ void cp16(uint32_t dst, const void* src) {
    asm volatile("cp.async.cg.shared.global [%0], [%1], 16;\n" :: "r"(dst), "l"(src));
}
#define CP_COMMIT() asm volatile("cp.async.commit_group;\n" ::: "memory")

__device__ __forceinline__ void ldsm4(uint32_t* r, uint32_t addr) {
    asm volatile("ldmatrix.sync.aligned.m8n8.x4.shared.b16 {%0,%1,%2,%3}, [%4];"
        : "=r"(r[0]), "=r"(r[1]), "=r"(r[2]), "=r"(r[3]) : "r"(addr));
}
__device__ __forceinline__ void ldsm4t(uint32_t* r, uint32_t addr) {
    asm volatile("ldmatrix.sync.aligned.m8n8.x4.trans.shared.b16 {%0,%1,%2,%3}, [%4];"
        : "=r"(r[0]), "=r"(r[1]), "=r"(r[2]), "=r"(r[3]) : "r"(addr));
}
__device__ __forceinline__ void mma16816(float* d, const uint32_t* a, const uint32_t* b) {
    asm volatile("mma.sync.aligned.m16n8k16.row.col.f32.f16.f16.f32 "
        "{%0,%1,%2,%3}, {%4,%5,%6,%7}, {%8,%9}, {%0,%1,%2,%3};"
        : "+f"(d[0]), "+f"(d[1]), "+f"(d[2]), "+f"(d[3])
        : "r"(a[0]), "r"(a[1]), "r"(a[2]), "r"(a[3]), "r"(b[0]), "r"(b[1]));
}
__device__ __forceinline__ uint32_t packh2(float e0, float e1) {
    uint32_t d;
    asm("cvt.rn.f16x2.f32 %0, %1, %2;" : "=r"(d) : "f"(e1), "f"(e0));
    return d;
}

// ------------------------- mask detect + pack --------------------------------
__global__ void detect_mask_kernel(const unsigned int* __restrict__ m) {
    __shared__ int sF, sO;
    if (threadIdx.x == 0) { sF = 0; sO = 0; }
    __syncthreads();
    bool f = false, o = false;
    for (int i = threadIdx.x; i < 2048; i += 256) {
        unsigned int w = m[i];
        if (w == 0u || w == 1u) continue;
        if (w == 0x3f800000u) f = true; else o = true;
    }
    if (f) sF = 1;
    if (o) sO = 1;
    __syncthreads();
    if (threadIdx.x == 0) g_mask_mode = sO ? 1 : (sF ? 2 : 0);
}

__global__ __launch_bounds__(256) void pack_mask(const void* __restrict__ mask) {
    int mode = g_mask_mode;
    #pragma unroll
    for (int p = 0; p < 4; p++) {
        int widx = blockIdx.x * 1024 + p * 256 + threadIdx.x;
        uint32_t bits = 0;
        if (mode == 1) {
            const uchar4* pp = (const uchar4*)mask + (size_t)widx * 8;
            #pragma unroll
            for (int q = 0; q < 8; q++) {
                uchar4 v = pp[q];
                bits |= (uint32_t)(v.x != 0) << (4*q)
                     |  (uint32_t)(v.y != 0) << (4*q+1)
                     |  (uint32_t)(v.z != 0) << (4*q+2)
                     |  (uint32_t)(v.w != 0) << (4*q+3);
            }
        } else if (mode == 2) {
            const float4* pp = (const float4*)mask + (size_t)widx * 8;
            #pragma unroll
            for (int q = 0; q < 8; q++) {
                float4 v = pp[q];
                bits |= (uint32_t)(v.x != 0.f) << (4*q)
                     |  (uint32_t)(v.y != 0.f) << (4*q+1)
                     |  (uint32_t)(v.z != 0.f) << (4*q+2)
                     |  (uint32_t)(v.w != 0.f) << (4*q+3);
            }
        } else {
            const int4* pp = (const int4*)mask + (size_t)widx * 8;
            #pragma unroll
            for (int q = 0; q < 8; q++) {
                int4 v = pp[q];
                bits |= (uint32_t)(v.x != 0) << (4*q)
                     |  (uint32_t)(v.y != 0) << (4*q+1)
                     |  (uint32_t)(v.z != 0) << (4*q+2)
                     |  (uint32_t)(v.w != 0) << (4*q+3);
            }
        }
        g_mb[widx] = bits;
    }
}

// ------------------------- prep kernels --------------------------------------
// fp32 -> fp16 convert (single), 4 float4/thread
__global__ __launch_bounds__(256) void cvt3_kernel(
    const float4* __restrict__ x0, const float4* __restrict__ x1,
    const float4* __restrict__ x2)
{
    int pl = blockIdx.y;
    const float4* __restrict__ src = (pl == 0) ? x0 : (pl == 1) ? x1 : x2;
    __half2* dst = reinterpret_cast<__half2*>(g_a + pl * APLANE);
    #pragma unroll
    for (int p = 0; p < 4; p++) {
        size_t i = (size_t)blockIdx.x * 1024 + p * 256 + threadIdx.x;
        float4 v = src[i];
        __half2 a, b;
        a.x = __float2half_rn(v.x); a.y = __float2half_rn(v.y);
        b.x = __float2half_rn(v.z); b.y = __float2half_rn(v.w);
        dst[i*2] = a; dst[i*2+1] = b;
    }
}

// 4 weight planes fp16: 0..2 = wq/wk/wv, 3 = wo transpose
__global__ __launch_bounds__(256) void prep_w4(
    const float* __restrict__ w0, const float* __restrict__ w1,
    const float* __restrict__ w2, const float* __restrict__ w3)
{
    int pl = blockIdx.z;
    int k = blockIdx.x * 256 + threadIdx.x;
    int n = blockIdx.y;
    float v;
    if (pl < 3) {
        const float* __restrict__ w = (pl == 0) ? w0 : (pl == 1) ? w1 : w2;
        float scale = (pl == 0) ? 0.125f : 1.0f;
        int h = n >> 6, d = n & 63;
        v = w[((size_t)h * HID_ + k) * D_ + d] * scale;
    } else {
        v = w3[(size_t)k * HID_ + n];
    }
    g_w[pl * WPLANE + (size_t)n * HID_ + k] = __float2half_rn(v);
}

// ------------------------- HMMA GEMM (fp16 single) ---------------------------
// Stage: A 8K + W 8K = 16KB; 2 stages = 32KB -> 2 CTAs/SM.
#define STG 16384
#define OFF_W 8192

__device__ __forceinline__ uint32_t taddr(uint32_t base, int row, int chunk) {
    return base + row * 64 + ((chunk ^ ((row >> 1) & 3)) << 4);
}

__device__ __forceinline__ void load_tile(uint32_t dstbase,
    const __half* __restrict__ src, int row0, int k0, int tid)
{
    #pragma unroll
    for (int p = 0; p < 2; p++) {
        int idx = tid + p * 256;
        int row = idx >> 2, ch = idx & 3;
        cp16(taddr(dstbase, row, ch),
             src + (size_t)(row0 + row) * HID_ + k0 + ch * 8);
    }
}

__device__ __forceinline__ void gemm_body(
    const __half* __restrict__ A, const __half* __restrict__ W,
    const float* __restrict__ bias, float bscale,
    float* __restrict__ out_ext, int sel)
{
    extern __shared__ char raw[];
    uint32_t sb = smem_u32(raw);

    int tid = threadIdx.x, lane = tid & 31, wid = tid >> 5;
    int wm = wid & 3, wn = wid >> 2;
    int m0 = blockIdx.x * 128, n0 = blockIdx.y * 128;
    int lrow = lane & 15, lsel = lane >> 4;

    float acc[2][8][4];
    #pragma unroll
    for (int a = 0; a < 2; a++)
        #pragma unroll
        for (int b = 0; b < 8; b++)
            #pragma unroll
            for (int c = 0; c < 4; c++) acc[a][b][c] = 0.f;

    load_tile(sb,         A, m0, 0, tid);
    load_tile(sb + OFF_W, W, n0, 0, tid);
    CP_COMMIT();

    const int NST = HID_ / 32;
    for (int i = 0; i < NST; i++) {
        if (i + 1 < NST) {
            uint32_t nb = sb + (uint32_t)((i + 1) & 1) * STG;
            int k0 = (i + 1) * 32;
            load_tile(nb,         A, m0, k0, tid);
            load_tile(nb + OFF_W, W, n0, k0, tid);
            CP_COMMIT();
            asm volatile("cp.async.wait_group 1;" ::: "memory");
        } else {
            asm volatile("cp.async.wait_group 0;" ::: "memory");
        }
        __syncthreads();

        uint32_t buf = sb + (uint32_t)(i & 1) * STG;
        #pragma unroll
        for (int kk = 0; kk < 2; kk++) {
            int chunk = (kk << 1) + lsel;
            uint32_t af[2][4];
            #pragma unroll
            for (int mf = 0; mf < 2; mf++)
                ldsm4(af[mf], taddr(buf, wm * 32 + mf * 16 + lrow, chunk));
            uint32_t wfr[8][2];
            #pragma unroll
            for (int j = 0; j < 4; j++) {
                uint32_t t4[4];
                ldsm4(t4, taddr(buf + OFF_W, wn * 64 + j * 16 + lrow, chunk));
                wfr[2*j][0] = t4[0]; wfr[2*j+1][0] = t4[1];
                wfr[2*j][1] = t4[2]; wfr[2*j+1][1] = t4[3];
            }
            #pragma unroll
            for (int mf = 0; mf < 2; mf++)
                #pragma unroll
                for (int nf = 0; nf < 8; nf++)
                    mma16816(acc[mf][nf], af[mf], wfr[nf]);
        }
        __syncthreads();
    }

    int gg = lane >> 2, t2 = (lane & 3) * 2;
    if (sel < 3) {
        __half* dst = (sel == 0) ? g_q : (sel == 1) ? g_k : g_v;
        #pragma unroll
        for (int mf = 0; mf < 2; mf++) {
            int row = m0 + wm * 32 + mf * 16 + gg;
            #pragma unroll
            for (int nf = 0; nf < 8; nf++) {
                int col = n0 + wn * 64 + nf * 8 + t2;
                float b0 = bias[col] * bscale, b1 = bias[col + 1] * bscale;
                __half2 hp;
                hp.x = __float2half_rn(acc[mf][nf][0] + b0);
                hp.y = __float2half_rn(acc[mf][nf][1] + b1);
                *reinterpret_cast<__half2*>(dst + (size_t)row * HID_ + col) = hp;
                hp.x = __float2half_rn(acc[mf][nf][2] + b0);
                hp.y = __float2half_rn(acc[mf][nf][3] + b1);
                *reinterpret_cast<__half2*>(dst + (size_t)(row+8) * HID_ + col) = hp;
            }
        }
    } else {
        #pragma unroll
        for (int mf = 0; mf < 2; mf++) {
            int row = m0 + wm * 32 + mf * 16 + gg;
            float* r0 = out_ext + (size_t)row * HID_ + n0 + wn * 64;
            float* r1 = r0 + 8 * HID_;
            #pragma unroll
            for (int nf = 0; nf < 8; nf++) {
                int col = nf * 8 + t2;
                float b0 = bias[n0 + wn * 64 + col]     * bscale;
                float b1 = bias[n0 + wn * 64 + col + 1] * bscale;
                *reinterpret_cast<float2*>(r0 + col) =
                    make_float2(acc[mf][nf][0] + b0, acc[mf][nf][1] + b1);
                *reinterpret_cast<float2*>(r1 + col) =
                    make_float2(acc[mf][nf][2] + b0, acc[mf][nf][3] + b1);
            }
        }
    }
}

__global__ __launch_bounds__(256, 2) void gemm_qkv(
    const float* __restrict__ bq, const float* __restrict__ bk,
    const float* __restrict__ bv)
{
    int sel = blockIdx.z;
    const float* bias = (sel == 0) ? bq : (sel == 1) ? bk : bv;
    float bscale = (sel == 0) ? 0.125f : 1.0f;
    gemm_body(g_a + sel * APLANE, g_w + sel * WPLANE, bias, bscale, nullptr, sel);
}

__global__ __launch_bounds__(256, 2) void gemm_out(
    const float* __restrict__ bo, float* __restrict__ out)
{
    gemm_body(g_a, g_w + 3 * WPLANE, bo, 1.0f, out, 3);
}

// ------------------------- HMMA flash attention (fp16 single) ----------------
// Q/K/P/V all single fp16. Stage = K 8KB + V 8KB = 16KB; 2 stages = 32KB.
#define ASTG 16384
#define ATT_SMEM (2*ASTG)

__device__ __forceinline__ uint32_t taddr128(uint32_t base, int row, int ch) {
    return base + row * 128 + ((ch ^ (row & 7)) << 4);
}

__device__ __forceinline__ void att_stage(uint32_t st, int b, int h, int t, int tid) {
    #pragma unroll
    for (int p = 0; p < 4; p++) {
        int idx = tid + p * 256;
        int arr = idx >> 9;            // 0 = K, 1 = V
        int row = (idx & 511) >> 3, ch = idx & 7;
        const __half* src = (arr ? g_v : g_k)
            + (size_t)(b * S_ + t * 64 + row) * HID_ + h * D_ + ch * 8;
        cp16(taddr128(st + arr * 8192, row, ch), src);
    }
}

__global__ __launch_bounds__(256, 2) void attn_mma()
{
    extern __shared__ char raw[];
    uint32_t sb = smem_u32(raw);

    int tid = threadIdx.x, lane = tid & 31, w = tid >> 5;
    int b = blockIdx.y >> 4, h = blockIdx.y & 15;
    int sq0 = blockIdx.x * 128;
    int lrow = lane & 15, lsel = lane >> 4;
    int g = lane >> 2, t4 = lane & 3;

    // Q -> buf0 (transient, 16KB exactly)
    #pragma unroll
    for (int p = 0; p < 4; p++) {
        int idx = tid + p * 256;
        int row = idx >> 3, ch = idx & 7;
        const __half* src = g_q
            + (size_t)(b * S_ + sq0 + row) * HID_ + h * D_ + ch * 8;
        cp16(taddr128(sb, row, ch), src);
    }
    CP_COMMIT();
    asm volatile("cp.async.wait_group 0;" ::: "memory");
    __syncthreads();

    uint32_t qf[4][4];
    #pragma unroll
    for (int kt = 0; kt < 4; kt++)
        ldsm4(qf[kt], taddr128(sb, w * 16 + lrow, 2 * kt + lsel));
    __syncthreads();

    att_stage(sb, b, h, 0, tid);
    CP_COMMIT();
    att_stage(sb + ASTG, b, h, 1, tid);
    CP_COMMIT();
    asm volatile("cp.async.wait_group 1;" ::: "memory");   // stage0 landed
    __syncthreads();

    float oc[8][4];
    #pragma unroll
    for (int n = 0; n < 8; n++)
        #pragma unroll
        for (int c = 0; c < 4; c++) oc[n][c] = 0.f;
    float l0 = 0.f, l1 = 0.f;

    for (int t = 0; t < S_ / 64; t++) {
        if (t > 0) {
            if (t + 1 < S_ / 64)
                att_stage(sb + (uint32_t)((t + 1) & 1) * ASTG, b, h, t + 1, tid);
            CP_COMMIT();
            asm volatile("cp.async.wait_group 1;" ::: "memory");
            __syncthreads();
        }
        uint32_t buf = sb + (uint32_t)(t & 1) * ASTG;

        float sc[8][4];
        #pragma unroll
        for (int n = 0; n < 8; n++)
            #pragma unroll
            for (int c = 0; c < 4; c++) sc[n][c] = 0.f;

        #pragma unroll
        for (int kt = 0; kt < 4; kt++) {
            uint32_t kf[8][2], tt[4];
            #pragma unroll
            for (int j = 0; j < 4; j++) {
                ldsm4(tt, taddr128(buf, j * 16 + lrow, 2 * kt + lsel));
                kf[2*j][0]=tt[0]; kf[2*j+1][0]=tt[1]; kf[2*j][1]=tt[2]; kf[2*j+1][1]=tt[3];
            }
            #pragma unroll
            for (int n = 0; n < 8; n++) mma16816(sc[n], qf[kt], kf[n]);
        }

        size_t mrow = ((size_t)b * S_ + sq0 + w * 16 + g) * (S_ / 32) + 2 * t;
        uint32_t w00 = g_mb[mrow], w01 = g_mb[mrow + 1];
        uint32_t w10 = g_mb[mrow + 8 * (S_ / 32)], w11 = g_mb[mrow + 8 * (S_ / 32) + 1];
        #pragma unroll
        for (int j = 0; j < 8; j++) {
            int bit = (8 * j + 2 * t4) & 31;
            uint32_t wa = (j < 4) ? w00 : w01;
            uint32_t wb = (j < 4) ? w10 : w11;
            if (!((wa >> bit) & 1))       sc[j][0] = -1.0e9f;
            if (!((wa >> (bit + 1)) & 1)) sc[j][1] = -1.0e9f;
            if (!((wb >> bit) & 1))       sc[j][2] = -1.0e9f;
            if (!((wb >> (bit + 1)) & 1)) sc[j][3] = -1.0e9f;
        }

        // fixed-shift softmax numerator
        #pragma unroll
        for (int j = 0; j < 8; j++) {
            sc[j][0] = __expf(sc[j][0]); l0 += sc[j][0];
            sc[j][1] = __expf(sc[j][1]); l0 += sc[j][1];
            sc[j][2] = __expf(sc[j][2]); l1 += sc[j][2];
            sc[j][3] = __expf(sc[j][3]); l1 += sc[j][3];
        }

        // P -> fp16 A-fragments
        uint32_t pf[4][4];
        #pragma unroll
        for (int j2 = 0; j2 < 4; j2++) {
            pf[j2][0] = packh2(sc[2*j2][0],   sc[2*j2][1]);
            pf[j2][1] = packh2(sc[2*j2][2],   sc[2*j2][3]);
            pf[j2][2] = packh2(sc[2*j2+1][0], sc[2*j2+1][1]);
            pf[j2][3] = packh2(sc[2*j2+1][2], sc[2*j2+1][3]);
        }

        #pragma unroll
        for (int j2 = 0; j2 < 4; j2++) {
            uint32_t vf[8][2], tt[4];
            #pragma unroll
            for (int np = 0; np < 4; np++) {
                ldsm4t(tt, taddr128(buf + 8192, j2 * 16 + lrow, 2 * np + lsel));
                vf[2*np][0]=tt[0]; vf[2*np][1]=tt[1]; vf[2*np+1][0]=tt[2]; vf[2*np+1][1]=tt[3];
            }
            #pragma unroll
            for (int n = 0; n < 8; n++) mma16816(oc[n], pf[j2], vf[n]);
        }
        __syncthreads();
    }

    l0 += __shfl_xor_sync(0xffffffffu, l0, 1);
    l0 += __shfl_xor_sync(0xffffffffu, l0, 2);
    l1 += __shfl_xor_sync(0xffffffffu, l1, 1);
    l1 += __shfl_xor_sync(0xffffffffu, l1, 2);
    float inv0 = 1.f / l0, inv1 = 1.f / l1;
    size_t base0 = (size_t)(b * S_ + sq0 + w * 16 + g) * HID_ + h * D_;
    size_t base1 = base0 + (size_t)8 * HID_;
    #pragma unroll
    for (int j = 0; j < 8; j++) {
        int col = 8 * j + 2 * t4;
        __half2 hp;
        hp.x = __float2half_rn(oc[j][0] * inv0);
        hp.y = __float2half_rn(oc[j][1] * inv0);
        *reinterpret_cast<__half2*>(g_a + base0 + col) = hp;
        hp.x = __float2half_rn(oc[j][2] * inv1);
        hp.y = __float2half_rn(oc[j][3] * inv1);
        *reinterpret_cast<__half2*>(g_a + base1 + col) = hp;
    }
}

// ------------------------- launch --------------------------------------------
extern "C" void kernel_launch(void* const* d_in, const int* in_sizes, int n_in,
                              void* d_out, int out_size)
{
    const float* qh  = (const float*)d_in[0];
    const float* kh  = (const float*)d_in[1];
    const float* vh  = (const float*)d_in[2];
    const void*  mask = d_in[3];
    const float* wq  = (const float*)d_in[4];
    const float* bq  = (const float*)d_in[5];
    const float* wk  = (const float*)d_in[6];
    const float* bk  = (const float*)d_in[7];
    const float* wv  = (const float*)d_in[8];
    const float* bv  = (const float*)d_in[9];
    const float* wo  = (const float*)d_in[10];
    const float* bo  = (const float*)d_in[11];
    float* out = (float*)d_out;

    cudaFuncSetAttribute(gemm_qkv, cudaFuncAttributeMaxDynamicSharedMemorySize, 2*STG);
    cudaFuncSetAttribute(gemm_out, cudaFuncAttributeMaxDynamicSharedMemorySize, 2*STG);
    cudaFuncSetAttribute(attn_mma, cudaFuncAttributeMaxDynamicSharedMemorySize, ATT_SMEM);

    detect_mask_kernel<<<1, 256>>>((const unsigned int*)mask);
    pack_mask<<<(B_*S_*(S_/32))/1024, 256>>>(mask);

    cvt3_kernel<<<dim3((NROWS_*HID_/4)/1024, 3), 256>>>(
        (const float4*)qh, (const float4*)kh, (const float4*)vh);
    prep_w4<<<dim3(HID_/256, HID_, 4), 256>>>(wq, wk, wv, wo);
    gemm_qkv<<<dim3(NROWS_/128, HID_/128, 3), 256, 2*STG>>>(bq, bk, bv);

    attn_mma<<<dim3(S_/128, B_*H_), 256, ATT_SMEM>>>();

    gemm_out<<<dim3(NROWS_/128, HID_/128), 256, 2*STG>>>(bo, out);
}

// round 12
// speedup vs baseline: 2.3646x; 1.0233x over previous
#include <cuda_runtime.h>
#include <cuda_fp16.h>
#include <cstdint>

#define B_ 4
#define S_ 2048
#define H_ 16
#define D_ 64
#define HID_ 1024
#define NROWS_ (B_*S_)
#define APLANE ((size_t)NROWS_*HID_)
#define WPLANE ((size_t)HID_*HID_)

// ------------------------- device scratch (no allocs) -----------------------
__device__ __half g_q[APLANE];     // Q fp16, pre-scaled 1/8
__device__ __half g_k[APLANE];
__device__ __half g_v[APLANE];
__device__ __half g_a[3*APLANE];   // GEMM A planes (q/k/v inputs; plane0 reused attn out)
__device__ __half g_w[4*WPLANE];   // weights fp16 [N][K]; plane3 = wo
__device__ uint32_t g_mb[(size_t)B_*S_*(S_/32)];
__device__ int g_mask_mode;

// ------------------------- helpers ------------------------------------------
__device__ __forceinline__ uint32_t smem_u32(const void* p) {
    uint32_t a;
    asm("{ .reg .u64 t; cvta.to.shared.u64 t, %1; cvt.u32.u64 %0, t; }"
        : "=r"(a) : "l"(p));
    return a;
}
__device__ __forceinline__ void cp16(uint32_t dst, const void* src) {
    asm volatile("cp.async.cg.shared.global [%0], [%1], 16;\n" :: "r"(dst), "l"(src));
}
#define CP_COMMIT() asm volatile("cp.async.commit_group;\n" ::: "memory")

__device__ __forceinline__ void ldsm4(uint32_t* r, uint32_t addr) {
    asm volatile("ldmatrix.sync.aligned.m8n8.x4.shared.b16 {%0,%1,%2,%3}, [%4];"
        : "=r"(r[0]), "=r"(r[1]), "=r"(r[2]), "=r"(r[3]) : "r"(addr));
}
__device__ __forceinline__ void ldsm4t(uint32_t* r, uint32_t addr) {
    asm volatile("ldmatrix.sync.aligned.m8n8.x4.trans.shared.b16 {%0,%1,%2,%3}, [%4];"
        : "=r"(r[0]), "=r"(r[1]), "=r"(r[2]), "=r"(r[3]) : "r"(addr));
}
__device__ __forceinline__ void mma16816(float* d, const uint32_t* a, const uint32_t* b) {
    asm volatile("mma.sync.aligned.m16n8k16.row.col.f32.f16.f16.f32 "
        "{%0,%1,%2,%3}, {%4,%5,%6,%7}, {%8,%9}, {%0,%1,%2,%3};"
        : "+f"(d[0]), "+f"(d[1]), "+f"(d[2]), "+f"(d[3])
        : "r"(a[0]), "r"(a[1]), "r"(a[2]), "r"(a[3]), "r"(b[0]), "r"(b[1]));
}
__device__ __forceinline__ uint32_t packh2(float e0, float e1) {
    uint32_t d;
    asm("cvt.rn.f16x2.f32 %0, %1, %2;" : "=r"(d) : "f"(e1), "f"(e0));
    return d;
}

// 128B-row swizzled smem tile addressing (conflict-free for all ldsm phases)
__device__ __forceinline__ uint32_t taddr128(uint32_t base, int row, int ch) {
    return base + row * 128 + ((ch ^ (row & 7)) << 4);
}

// ------------------------- mask detect ---------------------------------------
__global__ void detect_mask_kernel(const unsigned int* __restrict__ m) {
    __shared__ int sF, sO;
    if (threadIdx.x == 0) { sF = 0; sO = 0; }
    __syncthreads();
    bool f = false, o = false;
    for (int i = threadIdx.x; i < 2048; i += 256) {
        unsigned int w = m[i];
        if (w == 0u || w == 1u) continue;
        if (w == 0x3f800000u) f = true; else o = true;
    }
    if (f) sF = 1;
    if (o) sO = 1;
    __syncthreads();
    if (threadIdx.x == 0) g_mask_mode = sO ? 1 : (sF ? 2 : 0);
}

// ------------------------- fused preamble ------------------------------------
// Block ranges: [0,6144) cvt (3 planes x 2048), [6144,10240) weight prep
// (4 planes x 1024 n-rows), [10240,10752) mask pack.
#define CVT_BLKS 6144
#define PW_BLKS  4096

__global__ __launch_bounds__(256) void prep_all(
    const float4* __restrict__ x0, const float4* __restrict__ x1,
    const float4* __restrict__ x2,
    const float* __restrict__ w0, const float* __restrict__ w1,
    const float* __restrict__ w2, const float* __restrict__ w3,
    const void* __restrict__ mask)
{
    int bid = blockIdx.x, tid = threadIdx.x;
    if (bid < CVT_BLKS) {
        int pl = bid / 2048, blk = bid - pl * 2048;
        const float4* __restrict__ src = (pl == 0) ? x0 : (pl == 1) ? x1 : x2;
        __half2* dst = reinterpret_cast<__half2*>(g_a + pl * APLANE);
        #pragma unroll
        for (int p = 0; p < 4; p++) {
            size_t i = (size_t)blk * 1024 + p * 256 + tid;
            float4 v = src[i];
            __half2 a, b;
            a.x = __float2half_rn(v.x); a.y = __float2half_rn(v.y);
            b.x = __float2half_rn(v.z); b.y = __float2half_rn(v.w);
            dst[i*2] = a; dst[i*2+1] = b;
        }
    } else if (bid < CVT_BLKS + PW_BLKS) {
        int b2 = bid - CVT_BLKS;
        int pl = b2 >> 10, n = b2 & 1023;
        #pragma unroll
        for (int i = 0; i < 4; i++) {
            int k = i * 256 + tid;
            float v;
            if (pl < 3) {
                const float* __restrict__ w = (pl == 0) ? w0 : (pl == 1) ? w1 : w2;
                float scale = (pl == 0) ? 0.125f : 1.0f;
                int h = n >> 6, d = n & 63;
                v = w[((size_t)h * HID_ + k) * D_ + d] * scale;
            } else {
                v = w3[(size_t)k * HID_ + n];
            }
            g_w[pl * WPLANE + (size_t)n * HID_ + k] = __float2half_rn(v);
        }
    } else {
        int pk = bid - (CVT_BLKS + PW_BLKS);
        int mode = g_mask_mode;
        #pragma unroll
        for (int p = 0; p < 4; p++) {
            int widx = pk * 1024 + p * 256 + tid;
            uint32_t bits = 0;
            if (mode == 1) {
                const uchar4* pp = (const uchar4*)mask + (size_t)widx * 8;
                #pragma unroll
                for (int q = 0; q < 8; q++) {
                    uchar4 v = pp[q];
                    bits |= (uint32_t)(v.x != 0) << (4*q)
                         |  (uint32_t)(v.y != 0) << (4*q+1)
                         |  (uint32_t)(v.z != 0) << (4*q+2)
                         |  (uint32_t)(v.w != 0) << (4*q+3);
                }
            } else if (mode == 2) {
                const float4* pp = (const float4*)mask + (size_t)widx * 8;
                #pragma unroll
                for (int q = 0; q < 8; q++) {
                    float4 v = pp[q];
                    bits |= (uint32_t)(v.x != 0.f) << (4*q)
                         |  (uint32_t)(v.y != 0.f) << (4*q+1)
                         |  (uint32_t)(v.z != 0.f) << (4*q+2)
                         |  (uint32_t)(v.w != 0.f) << (4*q+3);
                }
            } else {
                const int4* pp = (const int4*)mask + (size_t)widx * 8;
                #pragma unroll
                for (int q = 0; q < 8; q++) {
                    int4 v = pp[q];
                    bits |= (uint32_t)(v.x != 0) << (4*q)
                         |  (uint32_t)(v.y != 0) << (4*q+1)
                         |  (uint32_t)(v.z != 0) << (4*q+2)
                         |  (uint32_t)(v.w != 0) << (4*q+3);
                }
            }
            g_mb[widx] = bits;
        }
    }
}

// ------------------------- HMMA GEMM (fp16, BK=64, 3-stage) ------------------
// Stage: A 16KB + W 16KB = 32KB; 3 stages = 96KB -> 2 CTAs/SM (192KB <= 228KB).
#define STG 32768
#define OFF_W 16384
#define GSMEM (3*STG)

__device__ __forceinline__ void load_tile64(uint32_t dstbase,
    const __half* __restrict__ src, int row0, int k0, int tid)
{
    #pragma unroll
    for (int p = 0; p < 4; p++) {
        int idx = tid + p * 256;
        int row = idx >> 3, ch = idx & 7;
        cp16(taddr128(dstbase, row, ch),
             src + (size_t)(row0 + row) * HID_ + k0 + ch * 8);
    }
}

__device__ __forceinline__ void gemm_body(
    const __half* __restrict__ A, const __half* __restrict__ W,
    const float* __restrict__ bias, float bscale,
    float* __restrict__ out_ext, int sel)
{
    extern __shared__ char raw[];
    uint32_t sb = smem_u32(raw);

    int tid = threadIdx.x, lane = tid & 31, wid = tid >> 5;
    int wm = wid & 3, wn = wid >> 2;
    int m0 = blockIdx.x * 128, n0 = blockIdx.y * 128;
    int lrow = lane & 15, lsel = lane >> 4;

    float acc[2][8][4];
    #pragma unroll
    for (int a = 0; a < 2; a++)
        #pragma unroll
        for (int b = 0; b < 8; b++)
            #pragma unroll
            for (int c = 0; c < 4; c++) acc[a][b][c] = 0.f;

    load_tile64(sb,         A, m0, 0, tid);
    load_tile64(sb + OFF_W, W, n0, 0, tid);
    CP_COMMIT();
    load_tile64(sb + STG,         A, m0, 64, tid);
    load_tile64(sb + STG + OFF_W, W, n0, 64, tid);
    CP_COMMIT();

    const int NST = HID_ / 64;   // 16
    for (int i = 0; i < NST; i++) {
        if (i + 1 < NST)
            asm volatile("cp.async.wait_group 1;" ::: "memory");
        else
            asm volatile("cp.async.wait_group 0;" ::: "memory");
        __syncthreads();
        if (i + 2 < NST) {
            uint32_t nb = sb + (uint32_t)((i + 2) % 3) * STG;
            int k0 = (i + 2) * 64;
            load_tile64(nb,         A, m0, k0, tid);
            load_tile64(nb + OFF_W, W, n0, k0, tid);
            CP_COMMIT();
        }
        uint32_t buf = sb + (uint32_t)(i % 3) * STG;
        #pragma unroll
        for (int kk = 0; kk < 4; kk++) {
            int chunk = (kk << 1) + lsel;
            uint32_t af[2][4];
            #pragma unroll
            for (int mf = 0; mf < 2; mf++)
                ldsm4(af[mf], taddr128(buf, wm * 32 + mf * 16 + lrow, chunk));
            uint32_t wfr[8][2];
            #pragma unroll
            for (int j = 0; j < 4; j++) {
                uint32_t t4[4];
                ldsm4(t4, taddr128(buf + OFF_W, wn * 64 + j * 16 + lrow, chunk));
                wfr[2*j][0] = t4[0]; wfr[2*j+1][0] = t4[1];
                wfr[2*j][1] = t4[2]; wfr[2*j+1][1] = t4[3];
            }
            #pragma unroll
            for (int mf = 0; mf < 2; mf++)
                #pragma unroll
                for (int nf = 0; nf < 8; nf++)
                    mma16816(acc[mf][nf], af[mf], wfr[nf]);
        }
    }

    int gg = lane >> 2, t2 = (lane & 3) * 2;
    if (sel < 3) {
        __half* dst = (sel == 0) ? g_q : (sel == 1) ? g_k : g_v;
        #pragma unroll
        for (int mf = 0; mf < 2; mf++) {
            int row = m0 + wm * 32 + mf * 16 + gg;
            #pragma unroll
            for (int nf = 0; nf < 8; nf++) {
                int col = n0 + wn * 64 + nf * 8 + t2;
                float b0 = bias[col] * bscale, b1 = bias[col + 1] * bscale;
                __half2 hp;
                hp.x = __float2half_rn(acc[mf][nf][0] + b0);
                hp.y = __float2half_rn(acc[mf][nf][1] + b1);
                *reinterpret_cast<__half2*>(dst + (size_t)row * HID_ + col) = hp;
                hp.x = __float2half_rn(acc[mf][nf][2] + b0);
                hp.y = __float2half_rn(acc[mf][nf][3] + b1);
                *reinterpret_cast<__half2*>(dst + (size_t)(row+8) * HID_ + col) = hp;
            }
        }
    } else {
        #pragma unroll
        for (int mf = 0; mf < 2; mf++) {
            int row = m0 + wm * 32 + mf * 16 + gg;
            float* r0 = out_ext + (size_t)row * HID_ + n0 + wn * 64;
            float* r1 = r0 + 8 * HID_;
            #pragma unroll
            for (int nf = 0; nf < 8; nf++) {
                int col = nf * 8 + t2;
                float b0 = bias[n0 + wn * 64 + col]     * bscale;
                float b1 = bias[n0 + wn * 64 + col + 1] * bscale;
                *reinterpret_cast<float2*>(r0 + col) =
                    make_float2(acc[mf][nf][0] + b0, acc[mf][nf][1] + b1);
                *reinterpret_cast<float2*>(r1 + col) =
                    make_float2(acc[mf][nf][2] + b0, acc[mf][nf][3] + b1);
            }
        }
    }
}

__global__ __launch_bounds__(256, 2) void gemm_qkv(
    const float* __restrict__ bq, const float* __restrict__ bk,
    const float* __restrict__ bv)
{
    int sel = blockIdx.z;
    const float* bias = (sel == 0) ? bq : (sel == 1) ? bk : bv;
    float bscale = (sel == 0) ? 0.125f : 1.0f;
    gemm_body(g_a + sel * APLANE, g_w + sel * WPLANE, bias, bscale, nullptr, sel);
}

__global__ __launch_bounds__(256, 2) void gemm_out(
    const float* __restrict__ bo, float* __restrict__ out)
{
    gemm_body(g_a, g_w + 3 * WPLANE, bo, 1.0f, out, 3);
}

// ------------------------- HMMA flash attention (fp16, 3-stage) --------------
// Stage = K 8KB + V 8KB = 16KB; 3 stages = 48KB -> 2 CTAs/SM.
#define ASTG 16384
#define ATT_SMEM (3*ASTG)

__device__ __forceinline__ void att_stage(uint32_t st, int b, int h, int t, int tid) {
    #pragma unroll
    for (int p = 0; p < 4; p++) {
        int idx = tid + p * 256;
        int arr = idx >> 9;            // 0 = K, 1 = V
        int row = (idx & 511) >> 3, ch = idx & 7;
        const __half* src = (arr ? g_v : g_k)
            + (size_t)(b * S_ + t * 64 + row) * HID_ + h * D_ + ch * 8;
        cp16(taddr128(st + arr * 8192, row, ch), src);
    }
}

__global__ __launch_bounds__(256, 2) void attn_mma()
{
    extern __shared__ char raw[];
    uint32_t sb = smem_u32(raw);

    int tid = threadIdx.x, lane = tid & 31, w = tid >> 5;
    int b = blockIdx.y >> 4, h = blockIdx.y & 15;
    int sq0 = blockIdx.x * 128;
    int lrow = lane & 15, lsel = lane >> 4;
    int g = lane >> 2, t4 = lane & 3;

    // Q -> buf0 (transient, 16KB)
    #pragma unroll
    for (int p = 0; p < 4; p++) {
        int idx = tid + p * 256;
        int row = idx >> 3, ch = idx & 7;
        cp16(taddr128(sb, row, ch),
             g_q + (size_t)(b * S_ + sq0 + row) * HID_ + h * D_ + ch * 8);
    }
    CP_COMMIT();
    asm volatile("cp.async.wait_group 0;" ::: "memory");
    __syncthreads();

    uint32_t qf[4][4];
    #pragma unroll
    for (int kt = 0; kt < 4; kt++)
        ldsm4(qf[kt], taddr128(sb, w * 16 + lrow, 2 * kt + lsel));
    __syncthreads();

    att_stage(sb, b, h, 0, tid);
    CP_COMMIT();
    att_stage(sb + ASTG, b, h, 1, tid);
    CP_COMMIT();

    float oc[8][4];
    #pragma unroll
    for (int n = 0; n < 8; n++)
        #pragma unroll
        for (int c = 0; c < 4; c++) oc[n][c] = 0.f;
    float l0 = 0.f, l1 = 0.f;

    const int NT = S_ / 64;   // 32... (S_=2048 -> 32? no: 2048/64 = 32) tiles
    for (int t = 0; t < NT; t++) {
        if (t + 1 < NT)
            asm volatile("cp.async.wait_group 1;" ::: "memory");
        else
            asm volatile("cp.async.wait_group 0;" ::: "memory");
        __syncthreads();
        if (t + 2 < NT) {
            att_stage(sb + (uint32_t)((t + 2) % 3) * ASTG, b, h, t + 2, tid);
            CP_COMMIT();
        }
        uint32_t buf = sb + (uint32_t)(t % 3) * ASTG;

        float sc[8][4];
        #pragma unroll
        for (int n = 0; n < 8; n++)
            #pragma unroll
            for (int c = 0; c < 4; c++) sc[n][c] = 0.f;

        #pragma unroll
        for (int kt = 0; kt < 4; kt++) {
            uint32_t kf[8][2], tt[4];
            #pragma unroll
            for (int j = 0; j < 4; j++) {
                ldsm4(tt, taddr128(buf, j * 16 + lrow, 2 * kt + lsel));
                kf[2*j][0]=tt[0]; kf[2*j+1][0]=tt[1]; kf[2*j][1]=tt[2]; kf[2*j+1][1]=tt[3];
            }
            #pragma unroll
            for (int n = 0; n < 8; n++) mma16816(sc[n], qf[kt], kf[n]);
        }

        size_t mrow = ((size_t)b * S_ + sq0 + w * 16 + g) * (S_ / 32) + 2 * t;
        uint32_t w00 = g_mb[mrow], w01 = g_mb[mrow + 1];
        uint32_t w10 = g_mb[mrow + 8 * (S_ / 32)], w11 = g_mb[mrow + 8 * (S_ / 32) + 1];
        #pragma unroll
        for (int j = 0; j < 8; j++) {
            int bit = (8 * j + 2 * t4) & 31;
            uint32_t wa = (j < 4) ? w00 : w01;
            uint32_t wb = (j < 4) ? w10 : w11;
            if (!((wa >> bit) & 1))       sc[j][0] = -1.0e9f;
            if (!((wa >> (bit + 1)) & 1)) sc[j][1] = -1.0e9f;
            if (!((wb >> bit) & 1))       sc[j][2] = -1.0e9f;
            if (!((wb >> (bit + 1)) & 1)) sc[j][3] = -1.0e9f;
        }

        #pragma unroll
        for (int j = 0; j < 8; j++) {
            sc[j][0] = __expf(sc[j][0]); l0 += sc[j][0];
            sc[j][1] = __expf(sc[j][1]); l0 += sc[j][1];
            sc[j][2] = __expf(sc[j][2]); l1 += sc[j][2];
            sc[j][3] = __expf(sc[j][3]); l1 += sc[j][3];
        }

        uint32_t pf[4][4];
        #pragma unroll
        for (int j2 = 0; j2 < 4; j2++) {
            pf[j2][0] = packh2(sc[2*j2][0],   sc[2*j2][1]);
            pf[j2][1] = packh2(sc[2*j2][2],   sc[2*j2][3]);
            pf[j2][2] = packh2(sc[2*j2+1][0], sc[2*j2+1][1]);
            pf[j2][3] = packh2(sc[2*j2+1][2], sc[2*j2+1][3]);
        }

        #pragma unroll
        for (int j2 = 0; j2 < 4; j2++) {
            uint32_t vf[8][2], tt[4];
            #pragma unroll
            for (int np = 0; np < 4; np++) {
                ldsm4t(tt, taddr128(buf + 8192, j2 * 16 + lrow, 2 * np + lsel));
                vf[2*np][0]=tt[0]; vf[2*np][1]=tt[1]; vf[2*np+1][0]=tt[2]; vf[2*np+1][1]=tt[3];
            }
            #pragma unroll
            for (int n = 0; n < 8; n++) mma16816(oc[n], pf[j2], vf[n]);
        }
    }

    l0 += __shfl_xor_sync(0xffffffffu, l0, 1);
    l0 += __shfl_xor_sync(0xffffffffu, l0, 2);
    l1 += __shfl_xor_sync(0xffffffffu, l1, 1);
    l1 += __shfl_xor_sync(0xffffffffu, l1, 2);
    float inv0 = 1.f / l0, inv1 = 1.f / l1;
    size_t base0 = (size_t)(b * S_ + sq0 + w * 16 + g) * HID_ + h * D_;
    size_t base1 = base0 + (size_t)8 * HID_;
    #pragma unroll
    for (int j = 0; j < 8; j++) {
        int col = 8 * j + 2 * t4;
        __half2 hp;
        hp.x = __float2half_rn(oc[j][0] * inv0);
        hp.y = __float2half_rn(oc[j][1] * inv0);
        *reinterpret_cast<__half2*>(g_a + base0 + col) = hp;
        hp.x = __float2half_rn(oc[j][2] * inv1);
        hp.y = __float2half_rn(oc[j][3] * inv1);
        *reinterpret_cast<__half2*>(g_a + base1 + col) = hp;
    }
}

// ------------------------- launch --------------------------------------------
extern "C" void kernel_launch(void* const* d_in, const int* in_sizes, int n_in,
                              void* d_out, int out_size)
{
    const float* qh  = (const float*)d_in[0];
    const float* kh  = (const float*)d_in[1];
    const float* vh  = (const float*)d_in[2];
    const void*  mask = d_in[3];
    const float* wq  = (const float*)d_in[4];
    const float* bq  = (const float*)d_in[5];
    const float* wk  = (const float*)d_in[6];
    const float* bk  = (const float*)d_in[7];
    const float* wv  = (const float*)d_in[8];
    const float* bv  = (const float*)d_in[9];
    const float* wo  = (const float*)d_in[10];
    const float* bo  = (const float*)d_in[11];
    float* out = (float*)d_out;

    cudaFuncSetAttribute(gemm_qkv, cudaFuncAttributeMaxDynamicSharedMemorySize, GSMEM);
    cudaFuncSetAttribute(gemm_out, cudaFuncAttributeMaxDynamicSharedMemorySize, GSMEM);
    cudaFuncSetAttribute(attn_mma, cudaFuncAttributeMaxDynamicSharedMemorySize, ATT_SMEM);

    detect_mask_kernel<<<1, 256>>>((const unsigned int*)mask);
    prep_all<<<CVT_BLKS + PW_BLKS + 512, 256>>>(
        (const float4*)qh, (const float4*)kh, (const float4*)vh,
        wq, wk, wv, wo, mask);

    gemm_qkv<<<dim3(NROWS_/128, HID_/128, 3), 256, GSMEM>>>(bq, bk, bv);

    attn_mma<<<dim3(S_/128, B_*H_), 256, ATT_SMEM>>>();

    gemm_out<<<dim3(NROWS_/128, HID_/128), 256, GSMEM>>>(bo, out);
}